// round 2
// baseline (speedup 1.0000x reference)
#include <cuda_runtime.h>
#include <math.h>
#include <stdint.h>

// ---------------------------------------------------------------------------
// Problem constants
//   B=8, L=1024 -> T = 8192 tokens
//   D_IN=1152, 4*D_IN=4608, D_E=256, C=4, K=2048, dpc=64, H=4096, 4H=16384
// Output layout (float32): x_vq [8192*4096] | idx as float [8192*4] | total,
// commitment, entropy
// ---------------------------------------------------------------------------
#define T_TOKENS 8192
#define D_IN     1152
#define D_H1     4608
#define D_E      256
#define NC       4
#define NK       2048
#define DPC      64
#define D_H3     16384
#define D_OUT    4096

#define XVQ_ELEMS   (T_TOKENS * D_OUT)          // 33554432
#define IDX_ELEMS   (T_TOKENS * NC)             // 32768

// Scratch (device globals: allocation-free rule)
__device__ float g_h1[(size_t)T_TOKENS * D_H1];     // 151 MB
__device__ float g_z [(size_t)T_TOKENS * D_E];      // 8 MB
__device__ float g_zq[(size_t)T_TOKENS * D_E];      // 8 MB
__device__ float g_h3[(size_t)T_TOKENS * D_H3];     // 536 MB
__device__ float g_esq[NC * NK];
__device__ int   g_counts[NC * NK];
__device__ float g_part[256];

// ---------------------------------------------------------------------------
// Exact GELU (matches jax.nn.gelu approximate=False)
// ---------------------------------------------------------------------------
__device__ __forceinline__ float gelu_exact(float x) {
    return 0.5f * x * (1.0f + erff(x * 0.70710678118654752440f));
}

// ---------------------------------------------------------------------------
// fp32 SGEMM: C[M,N] = act(A[M,K] @ B[K,N] + bias[N])
// BM=BN=128, BK=8, 256 threads, 8x8 per-thread tile.
// Requires: M%128==0, N%128==0, K%8==0 (true for all 4 GEMMs here).
// ---------------------------------------------------------------------------
#define BM 128
#define BN 128
#define BKK 8
#define TM 8
#define TN 8

__global__ void __launch_bounds__(256)
sgemm_kernel(const float* __restrict__ A, const float* __restrict__ B,
             const float* __restrict__ bias, float* __restrict__ C,
             int M, int N, int K, int doGelu)
{
    __shared__ float As[BKK][BM];
    __shared__ float Bs[BKK][BN];

    const int tid = threadIdx.x;
    const int bx = blockIdx.x;   // N tile
    const int by = blockIdx.y;   // M tile

    const int tx = tid & 15;     // N dir
    const int ty = tid >> 4;     // M dir

    const int aRow  = tid >> 1;          // 0..127
    const int aCol4 = (tid & 1) * 4;     // 0 or 4
    const int bRow  = tid >> 5;          // 0..7
    const int bCol4 = (tid & 31) * 4;    // 0..124

    const float* Aptr = A + (size_t)(by * BM + aRow) * K + aCol4;
    const float* Bptr = B + (size_t)bRow * N + (size_t)bx * BN + bCol4;

    float acc[TM][TN];
#pragma unroll
    for (int i = 0; i < TM; i++)
#pragma unroll
        for (int j = 0; j < TN; j++) acc[i][j] = 0.0f;

    for (int k0 = 0; k0 < K; k0 += BKK) {
        float4 av = *(const float4*)Aptr;
        float4 bv = *(const float4*)Bptr;
        Aptr += BKK;
        Bptr += (size_t)BKK * N;

        As[aCol4 + 0][aRow] = av.x;
        As[aCol4 + 1][aRow] = av.y;
        As[aCol4 + 2][aRow] = av.z;
        As[aCol4 + 3][aRow] = av.w;
        *(float4*)&Bs[bRow][bCol4] = bv;
        __syncthreads();

#pragma unroll
        for (int k = 0; k < BKK; k++) {
            float a[TM], b[TN];
#pragma unroll
            for (int i = 0; i < TM; i++) a[i] = As[k][ty * TM + i];
#pragma unroll
            for (int j = 0; j < TN; j++) b[j] = Bs[k][tx * TN + j];
#pragma unroll
            for (int i = 0; i < TM; i++)
#pragma unroll
                for (int j = 0; j < TN; j++)
                    acc[i][j] = fmaf(a[i], b[j], acc[i][j]);
        }
        __syncthreads();
    }

    // Epilogue: bias + optional gelu, float4 stores
#pragma unroll
    for (int i = 0; i < TM; i++) {
        const int row = by * BM + ty * TM + i;
#pragma unroll
        for (int j4 = 0; j4 < TN; j4 += 4) {
            const int col = bx * BN + tx * TN + j4;
            float4 v;
            v.x = acc[i][j4 + 0] + __ldg(&bias[col + 0]);
            v.y = acc[i][j4 + 1] + __ldg(&bias[col + 1]);
            v.z = acc[i][j4 + 2] + __ldg(&bias[col + 2]);
            v.w = acc[i][j4 + 3] + __ldg(&bias[col + 3]);
            if (doGelu) {
                v.x = gelu_exact(v.x); v.y = gelu_exact(v.y);
                v.z = gelu_exact(v.z); v.w = gelu_exact(v.w);
            }
            *(float4*)(C + (size_t)row * N + col) = v;
        }
    }
}

// ---------------------------------------------------------------------------
// e_sq[c][k] = sum_d codebooks[c][k][d]^2
// ---------------------------------------------------------------------------
__global__ void esq_kernel(const float* __restrict__ cb, float* __restrict__ esq)
{
    int idx = blockIdx.x * blockDim.x + threadIdx.x;   // 0..8191
    if (idx >= NC * NK) return;
    const float* e = cb + (size_t)idx * DPC;
    float s = 0.0f;
#pragma unroll
    for (int d = 0; d < DPC; d++) s += e[d] * e[d];
    esq[idx] = s;
}

__global__ void zero_counts_kernel(int* __restrict__ counts)
{
    int idx = blockIdx.x * blockDim.x + threadIdx.x;
    if (idx < NC * NK) counts[idx] = 0;
}

// ---------------------------------------------------------------------------
// VQ: per (token, group) argmin over 2048 codes (64-dim), gather z_q,
// per-CTA commitment partial sum, counts via int atomics, idx -> out (float).
// grid = (T/128, 4), block = 128. One token per thread, z-row in registers.
// Distances use the reference formula z_sq - 2*dot + e_sq; first-min wins.
// ---------------------------------------------------------------------------
#define VQ_TB 128
#define VQ_KC 128

__global__ void __launch_bounds__(VQ_TB)
vq_kernel(const float* __restrict__ z, const float* __restrict__ codebooks,
          const float* __restrict__ esq, float* __restrict__ zq,
          float* __restrict__ out_idx, float* __restrict__ partials,
          int* __restrict__ counts)
{
    __shared__ float E[VQ_KC][DPC];   // 32 KB
    __shared__ float Esq_s[VQ_KC];
    __shared__ float red[VQ_TB];

    const int c   = blockIdx.y;
    const int tid = threadIdx.x;
    const int t   = blockIdx.x * VQ_TB + tid;

    // Load this token's group sub-vector into registers
    float zr[DPC];
    {
        const float4* zp = (const float4*)(z + (size_t)t * D_E + c * DPC);
#pragma unroll
        for (int q = 0; q < DPC / 4; q++) {
            float4 v = zp[q];
            zr[4 * q + 0] = v.x; zr[4 * q + 1] = v.y;
            zr[4 * q + 2] = v.z; zr[4 * q + 3] = v.w;
        }
    }
    float zsq = 0.0f;
#pragma unroll
    for (int d = 0; d < DPC; d++) zsq = fmaf(zr[d], zr[d], zsq);

    const float* cb = codebooks + (size_t)c * NK * DPC;

    float best = 3.4e38f;
    int   bidx = 0;

    for (int k0 = 0; k0 < NK; k0 += VQ_KC) {
        // Stage codebook chunk (coalesced float4 loads)
        for (int i = tid; i < VQ_KC * (DPC / 4); i += VQ_TB) {
            int row = i >> 4;          // DPC/4 == 16
            int q   = i & 15;
            float4 v = *(const float4*)(cb + (size_t)(k0 + row) * DPC + q * 4);
            *(float4*)&E[row][q * 4] = v;
        }
        Esq_s[tid] = esq[c * NK + k0 + tid];
        __syncthreads();

        for (int j = 0; j < VQ_KC; j++) {
            float d0 = 0.f, d1 = 0.f, d2 = 0.f, d3 = 0.f;
#pragma unroll
            for (int d = 0; d < DPC; d += 4) {
                d0 = fmaf(zr[d + 0], E[j][d + 0], d0);
                d1 = fmaf(zr[d + 1], E[j][d + 1], d1);
                d2 = fmaf(zr[d + 2], E[j][d + 2], d2);
                d3 = fmaf(zr[d + 3], E[j][d + 3], d3);
            }
            float dot  = (d0 + d1) + (d2 + d3);
            float dist = zsq - 2.0f * dot + Esq_s[j];
            if (dist < best) { best = dist; bidx = k0 + j; }
        }
        __syncthreads();
    }

    // Gather z_q and commitment partial
    const float* e = cb + (size_t)bidx * DPC;
    float4* zqp = (float4*)(zq + (size_t)t * D_E + c * DPC);
    float cs = 0.0f;
#pragma unroll
    for (int q = 0; q < DPC / 4; q++) {
        float4 ev = *(const float4*)(e + q * 4);
        zqp[q] = ev;
        float dx = zr[4 * q + 0] - ev.x;
        float dy = zr[4 * q + 1] - ev.y;
        float dz = zr[4 * q + 2] - ev.z;
        float dw = zr[4 * q + 3] - ev.w;
        cs += dx * dx + dy * dy + dz * dz + dw * dw;
    }

    atomicAdd(&counts[c * NK + bidx], 1);
    out_idx[(size_t)t * NC + c] = (float)bidx;

    // Deterministic block reduction of commitment partials
    red[tid] = cs;
    __syncthreads();
    for (int s = VQ_TB / 2; s > 0; s >>= 1) {
        if (tid < s) red[tid] += red[tid + s];
        __syncthreads();
    }
    if (tid == 0) partials[blockIdx.y * gridDim.x + blockIdx.x] = red[0];
}

// ---------------------------------------------------------------------------
// Finalize: commitment/total + entropy scalars (deterministic tree sums)
// ---------------------------------------------------------------------------
__global__ void __launch_bounds__(256)
finalize_kernel(const float* __restrict__ partials, int npart,
                const int* __restrict__ counts, float* __restrict__ out_scalars)
{
    __shared__ float sm[256];
    const int tid = threadIdx.x;

    float v = (tid < npart) ? partials[tid] : 0.0f;
    sm[tid] = v;
    __syncthreads();
    for (int s = 128; s > 0; s >>= 1) {
        if (tid < s) sm[tid] += sm[tid + s];
        __syncthreads();
    }
    if (tid == 0) {
        float commitment = 0.25f * sm[0] / (float)(T_TOKENS * D_E);
        out_scalars[0] = commitment;   // total
        out_scalars[1] = commitment;   // commitment
    }

    // entropy = mean_c [ -sum_k p log(p + 1e-10) ],  p = counts / 8192
    float ent_acc = 0.0f;
    for (int c = 0; c < NC; c++) {
        float s = 0.0f;
        for (int k = tid; k < NK; k += 256) {
            float p = (float)counts[c * NK + k] * (1.0f / 8192.0f);
            s -= p * logf(p + 1e-10f);
        }
        __syncthreads();
        sm[tid] = s;
        __syncthreads();
        for (int st = 128; st > 0; st >>= 1) {
            if (tid < st) sm[tid] += sm[tid + st];
            __syncthreads();
        }
        if (tid == 0) ent_acc += sm[0];
        __syncthreads();
    }
    if (tid == 0) out_scalars[2] = ent_acc * 0.25f;
}

// ---------------------------------------------------------------------------
// Host launcher (graph-capturable: kernel launches only, default stream)
// Input order: x, W1, b1, W2, b2, codebooks, W3, b3, W4, b4
// ---------------------------------------------------------------------------
extern "C" void kernel_launch(void* const* d_in, const int* in_sizes, int n_in,
                              void* d_out, int out_size)
{
    const float* x   = (const float*)d_in[0];
    const float* W1  = (const float*)d_in[1];
    const float* b1  = (const float*)d_in[2];
    const float* W2  = (const float*)d_in[3];
    const float* b2  = (const float*)d_in[4];
    const float* cb  = (const float*)d_in[5];
    const float* W3  = (const float*)d_in[6];
    const float* b3  = (const float*)d_in[7];
    const float* W4  = (const float*)d_in[8];
    const float* b4  = (const float*)d_in[9];

    float* out = (float*)d_out;

    float *h1, *z, *zq, *h3, *esq, *part;
    int* counts;
    cudaGetSymbolAddress((void**)&h1, g_h1);
    cudaGetSymbolAddress((void**)&z, g_z);
    cudaGetSymbolAddress((void**)&zq, g_zq);
    cudaGetSymbolAddress((void**)&h3, g_h3);
    cudaGetSymbolAddress((void**)&esq, g_esq);
    cudaGetSymbolAddress((void**)&part, g_part);
    cudaGetSymbolAddress((void**)&counts, g_counts);

    // 1) h1 = gelu(x @ W1 + b1)          [8192 x 4608]
    sgemm_kernel<<<dim3(D_H1 / BN, T_TOKENS / BM), 256>>>(
        x, W1, b1, h1, T_TOKENS, D_H1, D_IN, 1);

    // 2) z = h1 @ W2 + b2                [8192 x 256]
    sgemm_kernel<<<dim3(D_E / BN, T_TOKENS / BM), 256>>>(
        h1, W2, b2, z, T_TOKENS, D_E, D_H1, 0);

    // 3) code norms + zero counts
    esq_kernel<<<(NC * NK + 255) / 256, 256>>>(cb, esq);
    zero_counts_kernel<<<(NC * NK + 255) / 256, 256>>>(counts);

    // 4) VQ: argmin, gather z_q, idx -> out, commitment partials, counts
    vq_kernel<<<dim3(T_TOKENS / VQ_TB, NC), VQ_TB>>>(
        z, cb, esq, zq, out + XVQ_ELEMS, part, counts);

    // 5) scalars: total, commitment, entropy
    finalize_kernel<<<1, 256>>>(part, (T_TOKENS / VQ_TB) * NC, counts,
                                out + XVQ_ELEMS + IDX_ELEMS);

    // 6) h3 = gelu(zq @ W3 + b3)         [8192 x 16384]
    sgemm_kernel<<<dim3(D_H3 / BN, T_TOKENS / BM), 256>>>(
        zq, W3, b3, h3, T_TOKENS, D_H3, D_E, 1);

    // 7) x_vq = h3 @ W4 + b4 -> out      [8192 x 4096]
    sgemm_kernel<<<dim3(D_OUT / BN, T_TOKENS / BM), 256>>>(
        h3, W4, b4, out, T_TOKENS, D_OUT, D_H3, 0);
}

// round 4
// speedup vs baseline: 2.4973x; 2.4973x over previous
#include <cuda_runtime.h>
#include <cuda_bf16.h>
#include <math.h>
#include <stdint.h>

// ---------------------------------------------------------------------------
// Constants: B=8, L=1024 -> T=8192; D_IN=1152, 4D_IN=4608, D_E=256, C=4,
// K=2048, dpc=64, H=4096, 4H=16384.
// Output (fp32): x_vq [8192*4096] | idx [8192*4] | total, commitment, entropy
// ---------------------------------------------------------------------------
#define T_TOKENS 8192
#define D_IN     1152
#define D_H1     4608
#define D_E      256
#define NC       4
#define NK       2048
#define DPC      64
#define D_H3     16384
#define D_OUT    4096

#define XVQ_ELEMS   (T_TOKENS * D_OUT)
#define IDX_ELEMS   (T_TOKENS * NC)

// Scratch (device globals)
__device__ float          g_h1[(size_t)T_TOKENS * D_H1];
__device__ float          g_z [(size_t)T_TOKENS * D_E];
__device__ __nv_bfloat16  g_zq_hi[(size_t)T_TOKENS * D_E];
__device__ __nv_bfloat16  g_zq_lo[(size_t)T_TOKENS * D_E];
__device__ __nv_bfloat16  g_h3_hi[(size_t)T_TOKENS * D_H3];   // 256 MB
__device__ __nv_bfloat16  g_h3_lo[(size_t)T_TOKENS * D_H3];   // 256 MB
__device__ __nv_bfloat16  g_w3_hi[(size_t)D_E * D_H3];
__device__ __nv_bfloat16  g_w3_lo[(size_t)D_E * D_H3];
__device__ __nv_bfloat16  g_w4_hi[(size_t)D_H3 * D_OUT];      // 128 MB
__device__ __nv_bfloat16  g_w4_lo[(size_t)D_H3 * D_OUT];      // 128 MB
__device__ float g_esq[NC * NK];
__device__ int   g_counts[NC * NK];
__device__ float g_part[256];

__device__ __forceinline__ float gelu_exact(float x) {
    return 0.5f * x * (1.0f + erff(x * 0.70710678118654752440f));
}

// ---------------------------------------------------------------------------
// fp32 -> (bf16 hi, bf16 lo) split conversion
// ---------------------------------------------------------------------------
__global__ void f2bf_split_kernel(const float* __restrict__ in,
                                  __nv_bfloat16* __restrict__ hi,
                                  __nv_bfloat16* __restrict__ lo, int n)
{
    int i = (blockIdx.x * blockDim.x + threadIdx.x) * 4;
    if (i >= n) return;
    float4 v = *(const float4*)(in + i);
    __nv_bfloat16 hx = __float2bfloat16_rn(v.x);
    __nv_bfloat16 hy = __float2bfloat16_rn(v.y);
    __nv_bfloat16 hz = __float2bfloat16_rn(v.z);
    __nv_bfloat16 hw = __float2bfloat16_rn(v.w);
    __nv_bfloat16 lx = __float2bfloat16_rn(v.x - __bfloat162float(hx));
    __nv_bfloat16 ly = __float2bfloat16_rn(v.y - __bfloat162float(hy));
    __nv_bfloat16 lz = __float2bfloat16_rn(v.z - __bfloat162float(hz));
    __nv_bfloat16 lw = __float2bfloat16_rn(v.w - __bfloat162float(hw));
    *(__nv_bfloat162*)(hi + i)     = __nv_bfloat162(hx, hy);
    *(__nv_bfloat162*)(hi + i + 2) = __nv_bfloat162(hz, hw);
    *(__nv_bfloat162*)(lo + i)     = __nv_bfloat162(lx, ly);
    *(__nv_bfloat162*)(lo + i + 2) = __nv_bfloat162(lz, lw);
}

// ---------------------------------------------------------------------------
// fp32 SGEMM for GEMM1/GEMM2 (argmin upstream must stay exact)
// ---------------------------------------------------------------------------
#define BM 128
#define BN 128
#define BKK 8
#define TM 8
#define TN 8

__global__ void __launch_bounds__(256)
sgemm_kernel(const float* __restrict__ A, const float* __restrict__ B,
             const float* __restrict__ bias, float* __restrict__ C,
             int M, int N, int K, int doGelu)
{
    __shared__ float As[BKK][BM];
    __shared__ float Bs[BKK][BN];

    const int tid = threadIdx.x;
    const int bx = blockIdx.x;
    const int by = blockIdx.y;
    const int tx = tid & 15;
    const int ty = tid >> 4;

    const int aRow  = tid >> 1;
    const int aCol4 = (tid & 1) * 4;
    const int bRow  = tid >> 5;
    const int bCol4 = (tid & 31) * 4;

    const float* Aptr = A + (size_t)(by * BM + aRow) * K + aCol4;
    const float* Bptr = B + (size_t)bRow * N + (size_t)bx * BN + bCol4;

    float acc[TM][TN];
#pragma unroll
    for (int i = 0; i < TM; i++)
#pragma unroll
        for (int j = 0; j < TN; j++) acc[i][j] = 0.0f;

    for (int k0 = 0; k0 < K; k0 += BKK) {
        float4 av = *(const float4*)Aptr;
        float4 bv = *(const float4*)Bptr;
        Aptr += BKK;
        Bptr += (size_t)BKK * N;

        As[aCol4 + 0][aRow] = av.x;
        As[aCol4 + 1][aRow] = av.y;
        As[aCol4 + 2][aRow] = av.z;
        As[aCol4 + 3][aRow] = av.w;
        *(float4*)&Bs[bRow][bCol4] = bv;
        __syncthreads();

#pragma unroll
        for (int k = 0; k < BKK; k++) {
            float a[TM], b[TN];
#pragma unroll
            for (int i = 0; i < TM; i++) a[i] = As[k][ty * TM + i];
#pragma unroll
            for (int j = 0; j < TN; j++) b[j] = Bs[k][tx * TN + j];
#pragma unroll
            for (int i = 0; i < TM; i++)
#pragma unroll
                for (int j = 0; j < TN; j++)
                    acc[i][j] = fmaf(a[i], b[j], acc[i][j]);
        }
        __syncthreads();
    }

#pragma unroll
    for (int i = 0; i < TM; i++) {
        const int row = by * BM + ty * TM + i;
#pragma unroll
        for (int j4 = 0; j4 < TN; j4 += 4) {
            const int col = bx * BN + tx * TN + j4;
            float4 v;
            v.x = acc[i][j4 + 0] + __ldg(&bias[col + 0]);
            v.y = acc[i][j4 + 1] + __ldg(&bias[col + 1]);
            v.z = acc[i][j4 + 2] + __ldg(&bias[col + 2]);
            v.w = acc[i][j4 + 3] + __ldg(&bias[col + 3]);
            if (doGelu) {
                v.x = gelu_exact(v.x); v.y = gelu_exact(v.y);
                v.z = gelu_exact(v.z); v.w = gelu_exact(v.w);
            }
            *(float4*)(C + (size_t)row * N + col) = v;
        }
    }
}

// ---------------------------------------------------------------------------
// Split-bf16 tensor-core GEMM: C = act(A @ B + bias) with
// A ~ A_hi + A_lo, B ~ B_hi + B_lo (bf16 pairs), fp32 accumulate.
// acc += A_hi*B_hi + A_hi*B_lo + A_lo*B_hi  (lo*lo dropped, ~2^-18)
// CTA 128x128, BK=32, 8 warps (4Mx2N), warp tile 32x64.
// mode 0: store fp32. mode 1: gelu -> split-bf16 store to outHi/outLo.
// Dynamic smem (~74 KB), double-buffered cp.async.
// ---------------------------------------------------------------------------
#define GBK 32
#define A_ST 40
#define B_ST 136
#define A_MAT (128 * A_ST)            // bf16 elems per A matrix per buf
#define B_MAT (GBK * B_ST)
#define SMEM_SPLIT_BYTES ((2 * 2 * A_MAT + 2 * 2 * B_MAT) * 2)

__device__ __forceinline__ void ldsm_x4(uint32_t* r, uint32_t addr) {
    asm volatile("ldmatrix.sync.aligned.m8n8.x4.shared.b16 {%0,%1,%2,%3}, [%4];"
                 : "=r"(r[0]), "=r"(r[1]), "=r"(r[2]), "=r"(r[3]) : "r"(addr));
}
__device__ __forceinline__ void ldsm_x4_t(uint32_t* r, uint32_t addr) {
    asm volatile("ldmatrix.sync.aligned.m8n8.x4.trans.shared.b16 {%0,%1,%2,%3}, [%4];"
                 : "=r"(r[0]), "=r"(r[1]), "=r"(r[2]), "=r"(r[3]) : "r"(addr));
}
__device__ __forceinline__ void mma_bf16(float* d, const uint32_t* a,
                                         uint32_t b0, uint32_t b1) {
    asm volatile(
        "mma.sync.aligned.m16n8k16.row.col.f32.bf16.bf16.f32 "
        "{%0,%1,%2,%3},{%4,%5,%6,%7},{%8,%9},{%0,%1,%2,%3};"
        : "+f"(d[0]), "+f"(d[1]), "+f"(d[2]), "+f"(d[3])
        : "r"(a[0]), "r"(a[1]), "r"(a[2]), "r"(a[3]), "r"(b0), "r"(b1));
}
__device__ __forceinline__ void cp16(uint32_t saddr, const void* g) {
    asm volatile("cp.async.cg.shared.global [%0], [%1], 16;"
                 :: "r"(saddr), "l"(g));
}

__global__ void __launch_bounds__(256)
split_gemm_kernel(const __nv_bfloat16* __restrict__ Ahi,
                  const __nv_bfloat16* __restrict__ Alo,
                  const __nv_bfloat16* __restrict__ Bhi,
                  const __nv_bfloat16* __restrict__ Blo,
                  const float* __restrict__ bias,
                  float* __restrict__ outF,
                  __nv_bfloat16* __restrict__ outHi,
                  __nv_bfloat16* __restrict__ outLo,
                  int M, int N, int K, int mode)
{
    extern __shared__ __nv_bfloat16 smem[];
    // Layout: [buf][mat] A tiles, then [buf][mat] B tiles
    __nv_bfloat16* sA = smem;                       // 2*2*A_MAT
    __nv_bfloat16* sB = smem + 4 * A_MAT;           // 2*2*B_MAT

    const int tid  = threadIdx.x;
    const int lane = tid & 31;
    const int warp = tid >> 5;
    const int wm   = warp >> 1;
    const int wn   = warp & 1;
    const int bm   = blockIdx.y * 128;
    const int bn   = blockIdx.x * 128;

    const int arow = tid >> 2;
    const int acol = (tid & 3) * 8;
    const int brow = tid >> 4;
    const int bcol = (tid & 15) * 8;

    const __nv_bfloat16* AgH = Ahi + (size_t)(bm + arow) * K + acol;
    const __nv_bfloat16* AgL = Alo + (size_t)(bm + arow) * K + acol;
    const __nv_bfloat16* BgH = Bhi + (size_t)brow * N + bn + bcol;
    const __nv_bfloat16* BgL = Blo + (size_t)brow * N + bn + bcol;

    // smem byte addresses for this thread's cp.async destinations
    const uint32_t saBase = (uint32_t)__cvta_generic_to_shared(
        &sA[arow * A_ST + acol]);
    const uint32_t sbBase = (uint32_t)__cvta_generic_to_shared(
        &sB[brow * B_ST + bcol]);

    float acc[2][8][4];
#pragma unroll
    for (int i = 0; i < 2; i++)
#pragma unroll
        for (int j = 0; j < 8; j++)
#pragma unroll
            for (int l = 0; l < 4; l++) acc[i][j][l] = 0.0f;

    const int KT = K / GBK;

#define ISSUE_TILE(kt, buf)                                                   \
    do {                                                                      \
        const size_t ka = (size_t)(kt) * GBK;                                 \
        const size_t kb = (size_t)(kt) * GBK * N;                             \
        const uint32_t aOff = (buf) * (2 * A_MAT * 2);                        \
        const uint32_t bOff = (buf) * (2 * B_MAT * 2);                        \
        cp16(saBase + aOff, AgH + ka);                                        \
        cp16(saBase + aOff + 64 * A_ST * 2, AgH + ka + (size_t)64 * K);       \
        cp16(saBase + aOff + A_MAT * 2, AgL + ka);                            \
        cp16(saBase + aOff + A_MAT * 2 + 64 * A_ST * 2,                       \
             AgL + ka + (size_t)64 * K);                                      \
        cp16(sbBase + bOff, BgH + kb);                                        \
        cp16(sbBase + bOff + 16 * B_ST * 2, BgH + kb + (size_t)16 * N);       \
        cp16(sbBase + bOff + B_MAT * 2, BgL + kb);                            \
        cp16(sbBase + bOff + B_MAT * 2 + 16 * B_ST * 2,                       \
             BgL + kb + (size_t)16 * N);                                      \
        asm volatile("cp.async.commit_group;");                               \
    } while (0)

    ISSUE_TILE(0, 0);

    for (int kt = 0; kt < KT; kt++) {
        const int buf = kt & 1;
        if (kt + 1 < KT) {
            ISSUE_TILE(kt + 1, buf ^ 1);
            asm volatile("cp.async.wait_group 1;");
        } else {
            asm volatile("cp.async.wait_group 0;");
        }
        __syncthreads();

        const __nv_bfloat16* cAhi = sA + buf * 2 * A_MAT;
        const __nv_bfloat16* cAlo = cAhi + A_MAT;
        const __nv_bfloat16* cBhi = sB + buf * 2 * B_MAT;
        const __nv_bfloat16* cBlo = cBhi + B_MAT;

#pragma unroll
        for (int ks = 0; ks < 2; ks++) {
            uint32_t aH[2][4], aL[2][4];
#pragma unroll
            for (int mt = 0; mt < 2; mt++) {
                int row = wm * 32 + mt * 16 + (lane & 15);
                int col = ks * 16 + (lane >> 4) * 8;
                ldsm_x4(aH[mt], (uint32_t)__cvta_generic_to_shared(
                                    &cAhi[row * A_ST + col]));
                ldsm_x4(aL[mt], (uint32_t)__cvta_generic_to_shared(
                                    &cAlo[row * A_ST + col]));
            }
#pragma unroll
            for (int nt = 0; nt < 4; nt++) {
                int krow = ks * 16 + (lane & 15);
                int ncol = wn * 64 + nt * 16 + (lane >> 4) * 8;
                uint32_t bH[4], bL[4];
                ldsm_x4_t(bH, (uint32_t)__cvta_generic_to_shared(
                                  &cBhi[krow * B_ST + ncol]));
                ldsm_x4_t(bL, (uint32_t)__cvta_generic_to_shared(
                                  &cBlo[krow * B_ST + ncol]));
#pragma unroll
                for (int mt = 0; mt < 2; mt++) {
                    float* a0 = acc[mt][nt * 2 + 0];
                    float* a1 = acc[mt][nt * 2 + 1];
                    mma_bf16(a0, aH[mt], bH[0], bH[1]);
                    mma_bf16(a1, aH[mt], bH[2], bH[3]);
                    mma_bf16(a0, aH[mt], bL[0], bL[1]);
                    mma_bf16(a1, aH[mt], bL[2], bL[3]);
                    mma_bf16(a0, aL[mt], bH[0], bH[1]);
                    mma_bf16(a1, aL[mt], bH[2], bH[3]);
                }
            }
        }
        __syncthreads();
    }
#undef ISSUE_TILE

    // Epilogue
#pragma unroll
    for (int mt = 0; mt < 2; mt++) {
        const int r0 = bm + wm * 32 + mt * 16 + (lane >> 2);
#pragma unroll
        for (int nt8 = 0; nt8 < 8; nt8++) {
            const int col = bn + wn * 64 + nt8 * 8 + (lane & 3) * 2;
            const float bx = __ldg(&bias[col]);
            const float by = __ldg(&bias[col + 1]);
            float v0 = acc[mt][nt8][0] + bx;
            float v1 = acc[mt][nt8][1] + by;
            float v2 = acc[mt][nt8][2] + bx;
            float v3 = acc[mt][nt8][3] + by;
            if (mode == 1) {
                v0 = gelu_exact(v0); v1 = gelu_exact(v1);
                v2 = gelu_exact(v2); v3 = gelu_exact(v3);
                __nv_bfloat16 h0 = __float2bfloat16_rn(v0);
                __nv_bfloat16 h1 = __float2bfloat16_rn(v1);
                __nv_bfloat16 h2 = __float2bfloat16_rn(v2);
                __nv_bfloat16 h3v = __float2bfloat16_rn(v3);
                __nv_bfloat16 l0 = __float2bfloat16_rn(v0 - __bfloat162float(h0));
                __nv_bfloat16 l1 = __float2bfloat16_rn(v1 - __bfloat162float(h1));
                __nv_bfloat16 l2 = __float2bfloat16_rn(v2 - __bfloat162float(h2));
                __nv_bfloat16 l3 = __float2bfloat16_rn(v3 - __bfloat162float(h3v));
                *(__nv_bfloat162*)(outHi + (size_t)r0 * N + col) =
                    __nv_bfloat162(h0, h1);
                *(__nv_bfloat162*)(outHi + (size_t)(r0 + 8) * N + col) =
                    __nv_bfloat162(h2, h3v);
                *(__nv_bfloat162*)(outLo + (size_t)r0 * N + col) =
                    __nv_bfloat162(l0, l1);
                *(__nv_bfloat162*)(outLo + (size_t)(r0 + 8) * N + col) =
                    __nv_bfloat162(l2, l3);
            } else {
                *(float2*)(outF + (size_t)r0 * N + col)       = make_float2(v0, v1);
                *(float2*)(outF + (size_t)(r0 + 8) * N + col) = make_float2(v2, v3);
            }
        }
    }
}

// ---------------------------------------------------------------------------
// e_sq, counts init
// ---------------------------------------------------------------------------
__global__ void esq_kernel(const float* __restrict__ cb, float* __restrict__ esq)
{
    int idx = blockIdx.x * blockDim.x + threadIdx.x;
    if (idx >= NC * NK) return;
    const float* e = cb + (size_t)idx * DPC;
    float s = 0.0f;
#pragma unroll
    for (int d = 0; d < DPC; d++) s += e[d] * e[d];
    esq[idx] = s;
}

__global__ void zero_counts_kernel(int* __restrict__ counts)
{
    int idx = blockIdx.x * blockDim.x + threadIdx.x;
    if (idx < NC * NK) counts[idx] = 0;
}

// ---------------------------------------------------------------------------
// VQ: fp32 argmin (exact), z_q emitted as split bf16 (hi, lo)
// ---------------------------------------------------------------------------
#define VQ_TB 128
#define VQ_KC 128

__global__ void __launch_bounds__(VQ_TB)
vq_kernel(const float* __restrict__ z, const float* __restrict__ codebooks,
          const float* __restrict__ esq,
          __nv_bfloat16* __restrict__ zqHi, __nv_bfloat16* __restrict__ zqLo,
          float* __restrict__ out_idx, float* __restrict__ partials,
          int* __restrict__ counts)
{
    __shared__ float E[VQ_KC][DPC];
    __shared__ float Esq_s[VQ_KC];
    __shared__ float red[VQ_TB];

    const int c   = blockIdx.y;
    const int tid = threadIdx.x;
    const int t   = blockIdx.x * VQ_TB + tid;

    float zr[DPC];
    {
        const float4* zp = (const float4*)(z + (size_t)t * D_E + c * DPC);
#pragma unroll
        for (int q = 0; q < DPC / 4; q++) {
            float4 v = zp[q];
            zr[4 * q + 0] = v.x; zr[4 * q + 1] = v.y;
            zr[4 * q + 2] = v.z; zr[4 * q + 3] = v.w;
        }
    }
    float zsq = 0.0f;
#pragma unroll
    for (int d = 0; d < DPC; d++) zsq = fmaf(zr[d], zr[d], zsq);

    const float* cb = codebooks + (size_t)c * NK * DPC;

    float best = 3.4e38f;
    int   bidx = 0;

    for (int k0 = 0; k0 < NK; k0 += VQ_KC) {
        for (int i = tid; i < VQ_KC * (DPC / 4); i += VQ_TB) {
            int row = i >> 4;
            int q   = i & 15;
            float4 v = *(const float4*)(cb + (size_t)(k0 + row) * DPC + q * 4);
            *(float4*)&E[row][q * 4] = v;
        }
        Esq_s[tid] = esq[c * NK + k0 + tid];
        __syncthreads();

        for (int j = 0; j < VQ_KC; j++) {
            float d0 = 0.f, d1 = 0.f, d2 = 0.f, d3 = 0.f;
#pragma unroll
            for (int d = 0; d < DPC; d += 4) {
                d0 = fmaf(zr[d + 0], E[j][d + 0], d0);
                d1 = fmaf(zr[d + 1], E[j][d + 1], d1);
                d2 = fmaf(zr[d + 2], E[j][d + 2], d2);
                d3 = fmaf(zr[d + 3], E[j][d + 3], d3);
            }
            float dot  = (d0 + d1) + (d2 + d3);
            float dist = zsq - 2.0f * dot + Esq_s[j];
            if (dist < best) { best = dist; bidx = k0 + j; }
        }
        __syncthreads();
    }

    const float* e = cb + (size_t)bidx * DPC;
    __nv_bfloat16* zh = zqHi + (size_t)t * D_E + c * DPC;
    __nv_bfloat16* zl = zqLo + (size_t)t * D_E + c * DPC;
    float cs = 0.0f;
#pragma unroll
    for (int q = 0; q < DPC / 4; q++) {
        float4 ev = *(const float4*)(e + q * 4);
        __nv_bfloat16 hx = __float2bfloat16_rn(ev.x);
        __nv_bfloat16 hy = __float2bfloat16_rn(ev.y);
        __nv_bfloat16 hz = __float2bfloat16_rn(ev.z);
        __nv_bfloat16 hw = __float2bfloat16_rn(ev.w);
        *(__nv_bfloat162*)(zh + 4 * q)     = __nv_bfloat162(hx, hy);
        *(__nv_bfloat162*)(zh + 4 * q + 2) = __nv_bfloat162(hz, hw);
        *(__nv_bfloat162*)(zl + 4 * q) = __nv_bfloat162(
            __float2bfloat16_rn(ev.x - __bfloat162float(hx)),
            __float2bfloat16_rn(ev.y - __bfloat162float(hy)));
        *(__nv_bfloat162*)(zl + 4 * q + 2) = __nv_bfloat162(
            __float2bfloat16_rn(ev.z - __bfloat162float(hz)),
            __float2bfloat16_rn(ev.w - __bfloat162float(hw)));
        float dx = zr[4 * q + 0] - ev.x;
        float dy = zr[4 * q + 1] - ev.y;
        float dz = zr[4 * q + 2] - ev.z;
        float dw = zr[4 * q + 3] - ev.w;
        cs += dx * dx + dy * dy + dz * dz + dw * dw;
    }

    atomicAdd(&counts[c * NK + bidx], 1);
    out_idx[(size_t)t * NC + c] = (float)bidx;

    red[tid] = cs;
    __syncthreads();
    for (int s = VQ_TB / 2; s > 0; s >>= 1) {
        if (tid < s) red[tid] += red[tid + s];
        __syncthreads();
    }
    if (tid == 0) partials[blockIdx.y * gridDim.x + blockIdx.x] = red[0];
}

// ---------------------------------------------------------------------------
// Finalize scalars
// ---------------------------------------------------------------------------
__global__ void __launch_bounds__(256)
finalize_kernel(const float* __restrict__ partials, int npart,
                const int* __restrict__ counts, float* __restrict__ out_scalars)
{
    __shared__ float sm[256];
    const int tid = threadIdx.x;

    float v = (tid < npart) ? partials[tid] : 0.0f;
    sm[tid] = v;
    __syncthreads();
    for (int s = 128; s > 0; s >>= 1) {
        if (tid < s) sm[tid] += sm[tid + s];
        __syncthreads();
    }
    if (tid == 0) {
        float commitment = 0.25f * sm[0] / (float)(T_TOKENS * D_E);
        out_scalars[0] = commitment;
        out_scalars[1] = commitment;
    }

    float ent_acc = 0.0f;
    for (int c = 0; c < NC; c++) {
        float s = 0.0f;
        for (int k = tid; k < NK; k += 256) {
            float p = (float)counts[c * NK + k] * (1.0f / 8192.0f);
            s -= p * logf(p + 1e-10f);
        }
        __syncthreads();
        sm[tid] = s;
        __syncthreads();
        for (int st = 128; st > 0; st >>= 1) {
            if (tid < st) sm[tid] += sm[tid + st];
            __syncthreads();
        }
        if (tid == 0) ent_acc += sm[0];
        __syncthreads();
    }
    if (tid == 0) out_scalars[2] = ent_acc * 0.25f;
}

// ---------------------------------------------------------------------------
// Host launcher. Inputs: x, W1, b1, W2, b2, codebooks, W3, b3, W4, b4
// ---------------------------------------------------------------------------
extern "C" void kernel_launch(void* const* d_in, const int* in_sizes, int n_in,
                              void* d_out, int out_size)
{
    const float* x   = (const float*)d_in[0];
    const float* W1  = (const float*)d_in[1];
    const float* b1  = (const float*)d_in[2];
    const float* W2  = (const float*)d_in[3];
    const float* b2  = (const float*)d_in[4];
    const float* cb  = (const float*)d_in[5];
    const float* W3  = (const float*)d_in[6];
    const float* b3  = (const float*)d_in[7];
    const float* W4  = (const float*)d_in[8];
    const float* b4  = (const float*)d_in[9];

    float* out = (float*)d_out;

    float *h1, *z, *esq, *part;
    __nv_bfloat16 *zqH, *zqL, *h3H, *h3L, *w3H, *w3L, *w4H, *w4L;
    int* counts;
    cudaGetSymbolAddress((void**)&h1,  g_h1);
    cudaGetSymbolAddress((void**)&z,   g_z);
    cudaGetSymbolAddress((void**)&zqH, g_zq_hi);
    cudaGetSymbolAddress((void**)&zqL, g_zq_lo);
    cudaGetSymbolAddress((void**)&h3H, g_h3_hi);
    cudaGetSymbolAddress((void**)&h3L, g_h3_lo);
    cudaGetSymbolAddress((void**)&w3H, g_w3_hi);
    cudaGetSymbolAddress((void**)&w3L, g_w3_lo);
    cudaGetSymbolAddress((void**)&w4H, g_w4_hi);
    cudaGetSymbolAddress((void**)&w4L, g_w4_lo);
    cudaGetSymbolAddress((void**)&esq, g_esq);
    cudaGetSymbolAddress((void**)&part, g_part);
    cudaGetSymbolAddress((void**)&counts, g_counts);

    // Allow large dynamic smem for the split GEMM (no-op after first call)
    cudaFuncSetAttribute(split_gemm_kernel,
                         cudaFuncAttributeMaxDynamicSharedMemorySize,
                         SMEM_SPLIT_BYTES);

    // 0) weight split conversions
    {
        int n3 = D_E * D_H3;
        int n4 = D_H3 * D_OUT;
        f2bf_split_kernel<<<(n3 / 4 + 255) / 256, 256>>>(W3, w3H, w3L, n3);
        f2bf_split_kernel<<<(n4 / 4 + 255) / 256, 256>>>(W4, w4H, w4L, n4);
    }

    // 1) h1 = gelu(x @ W1 + b1)   fp32 exact
    sgemm_kernel<<<dim3(D_H1 / BN, T_TOKENS / BM), 256>>>(
        x, W1, b1, h1, T_TOKENS, D_H1, D_IN, 1);

    // 2) z = h1 @ W2 + b2         fp32 exact
    sgemm_kernel<<<dim3(D_E / BN, T_TOKENS / BM), 256>>>(
        h1, W2, b2, z, T_TOKENS, D_E, D_H1, 0);

    // 3) code norms + zero counts
    esq_kernel<<<(NC * NK + 255) / 256, 256>>>(cb, esq);
    zero_counts_kernel<<<(NC * NK + 255) / 256, 256>>>(counts);

    // 4) VQ (fp32 argmin, split-bf16 z_q)
    vq_kernel<<<dim3(T_TOKENS / VQ_TB, NC), VQ_TB>>>(
        z, cb, esq, zqH, zqL, out + XVQ_ELEMS, part, counts);

    // 5) scalars
    finalize_kernel<<<1, 256>>>(part, (T_TOKENS / VQ_TB) * NC, counts,
                                out + XVQ_ELEMS + IDX_ELEMS);

    // 6) h3 = gelu(zq @ W3 + b3)  split-bf16 tensor cores -> split h3
    split_gemm_kernel<<<dim3(D_H3 / 128, T_TOKENS / 128), 256,
                        SMEM_SPLIT_BYTES>>>(
        zqH, zqL, w3H, w3L, b3, nullptr, h3H, h3L,
        T_TOKENS, D_H3, D_E, 1);

    // 7) x_vq = h3 @ W4 + b4 -> out  split-bf16 tensor cores
    split_gemm_kernel<<<dim3(D_OUT / 128, T_TOKENS / 128), 256,
                        SMEM_SPLIT_BYTES>>>(
        h3H, h3L, w4H, w4L, b4, out, nullptr, nullptr,
        T_TOKENS, D_OUT, D_H3, 0);
}

// round 6
// speedup vs baseline: 2.8274x; 1.1322x over previous
#include <cuda_runtime.h>
#include <cuda_bf16.h>
#include <math.h>
#include <stdint.h>

// ---------------------------------------------------------------------------
// Constants: T=8192; D_IN=1152, 4D_IN=4608, D_E=256, C=4, K=2048, dpc=64,
// H=4096, 4H=16384.
// Output (fp32): x_vq [8192*4096] | idx [8192*4] | total, commitment, entropy
// ---------------------------------------------------------------------------
#define T_TOKENS 8192
#define D_IN     1152
#define D_H1     4608
#define D_E      256
#define NC       4
#define NK       2048
#define DPC      64
#define D_H3     16384
#define D_OUT    4096

#define XVQ_ELEMS   (T_TOKENS * D_OUT)
#define IDX_ELEMS   (T_TOKENS * NC)

// Scratch
__device__ float          g_h1[(size_t)T_TOKENS * D_H1];
__device__ float          g_z [(size_t)T_TOKENS * D_E];
__device__ __nv_bfloat16  g_zq_hi[(size_t)T_TOKENS * D_E];
__device__ __nv_bfloat16  g_zq_lo[(size_t)T_TOKENS * D_E];
__device__ __nv_bfloat16  g_h3_hi[(size_t)T_TOKENS * D_H3];
__device__ __nv_bfloat16  g_h3_lo[(size_t)T_TOKENS * D_H3];
__device__ __nv_bfloat16  g_w3_hi[(size_t)D_E * D_H3];
__device__ __nv_bfloat16  g_w3_lo[(size_t)D_E * D_H3];
__device__ __nv_bfloat16  g_w4_hi[(size_t)D_H3 * D_OUT];
__device__ __nv_bfloat16  g_w4_lo[(size_t)D_H3 * D_OUT];
__device__ float g_esq[NC * NK];
__device__ int   g_counts[NC * NK];
__device__ float g_part[256];

__device__ __forceinline__ float gelu_exact(float x) {
    return 0.5f * x * (1.0f + erff(x * 0.70710678118654752440f));
}

// ---------------------------------------------------------------------------
// fp32 -> (bf16 hi, bf16 lo) split conversion (weights for GEMM3/4)
// ---------------------------------------------------------------------------
__global__ void f2bf_split_kernel(const float* __restrict__ in,
                                  __nv_bfloat16* __restrict__ hi,
                                  __nv_bfloat16* __restrict__ lo, int n)
{
    int i = (blockIdx.x * blockDim.x + threadIdx.x) * 4;
    if (i >= n) return;
    float4 v = *(const float4*)(in + i);
    __nv_bfloat16 hx = __float2bfloat16_rn(v.x);
    __nv_bfloat16 hy = __float2bfloat16_rn(v.y);
    __nv_bfloat16 hz = __float2bfloat16_rn(v.z);
    __nv_bfloat16 hw = __float2bfloat16_rn(v.w);
    *(__nv_bfloat162*)(hi + i)     = __nv_bfloat162(hx, hy);
    *(__nv_bfloat162*)(hi + i + 2) = __nv_bfloat162(hz, hw);
    *(__nv_bfloat162*)(lo + i) = __nv_bfloat162(
        __float2bfloat16_rn(v.x - __bfloat162float(hx)),
        __float2bfloat16_rn(v.y - __bfloat162float(hy)));
    *(__nv_bfloat162*)(lo + i + 2) = __nv_bfloat162(
        __float2bfloat16_rn(v.z - __bfloat162float(hz)),
        __float2bfloat16_rn(v.w - __bfloat162float(hw)));
}

// ---------------------------------------------------------------------------
// 3xTF32 split GEMM (GEMM1/GEMM2): near-fp32 precision on tensor cores.
// C[M,N] = act(A @ B + bias); A,B fp32; on-the-fly split into tf32 hi/lo.
// acc += Ah*Bh + Ah*Bl + Al*Bh  (lo*lo ~2^-22, dropped)
// CTA 128x128, BK=16, 256 threads, 8 warps (4M x 2N), warp tile 32x64.
// mma.sync.m16n8k8.tf32 with fp32 accumulate.
// ---------------------------------------------------------------------------
#define TBK 16
#define A_STW 20     // fp32 words per A smem row (16 + 4 pad) -> bank-free
#define B_STW 136    // fp32 words per B smem row (128 + 8 pad) -> bank-free

__device__ __forceinline__ uint32_t f2tf32(float v) {
    uint32_t r;
    asm("cvt.rna.tf32.f32 %0, %1;" : "=r"(r) : "f"(v));
    return r;
}
__device__ __forceinline__ void split_tf32(float v, uint32_t& h, uint32_t& l) {
    h = f2tf32(v);
    l = f2tf32(v - __uint_as_float(h));
}
__device__ __forceinline__ void mma_tf32(float* d, const uint32_t* a,
                                         uint32_t b0, uint32_t b1) {
    asm volatile(
        "mma.sync.aligned.m16n8k8.row.col.f32.tf32.tf32.f32 "
        "{%0,%1,%2,%3},{%4,%5,%6,%7},{%8,%9},{%0,%1,%2,%3};"
        : "+f"(d[0]), "+f"(d[1]), "+f"(d[2]), "+f"(d[3])
        : "r"(a[0]), "r"(a[1]), "r"(a[2]), "r"(a[3]), "r"(b0), "r"(b1));
}
__device__ __forceinline__ void cp16f(uint32_t saddr, const void* g) {
    asm volatile("cp.async.cg.shared.global [%0], [%1], 16;"
                 :: "r"(saddr), "l"(g));
}

__global__ void __launch_bounds__(256, 2)
tf32_gemm_kernel(const float* __restrict__ A, const float* __restrict__ B,
                 const float* __restrict__ bias, float* __restrict__ C,
                 int M, int N, int K, int doGelu)
{
    __shared__ float As[2][128 * A_STW];
    __shared__ float Bs[2][TBK * B_STW];

    const int tid  = threadIdx.x;
    const int lane = tid & 31;
    const int warp = tid >> 5;
    const int wm   = warp >> 1;      // 0..3
    const int wn   = warp & 1;       // 0..1
    const int gid  = lane >> 2;      // 0..7
    const int tid4 = lane & 3;       // 0..3
    const int bm   = blockIdx.y * 128;
    const int bn   = blockIdx.x * 128;

    // Global-load mapping
    const int aRow = tid >> 1;            // 0..127
    const int aQ   = (tid & 1) * 2;       // quad pair 0 or 2
    const int bK   = tid >> 5;            // 0..7 (+8 second)
    const int bC   = tid & 31;            // f4 col

    const float* Ag = A + (size_t)(bm + aRow) * K + aQ * 4;
    const float* Bg = B + (size_t)bK * N + bn + bC * 4;

    const uint32_t sa0 = (uint32_t)__cvta_generic_to_shared(
        &As[0][aRow * A_STW + aQ * 4]);
    const uint32_t sa1 = (uint32_t)__cvta_generic_to_shared(
        &As[1][aRow * A_STW + aQ * 4]);
    const uint32_t sb0 = (uint32_t)__cvta_generic_to_shared(
        &Bs[0][bK * B_STW + bC * 4]);
    const uint32_t sb1 = (uint32_t)__cvta_generic_to_shared(
        &Bs[1][bK * B_STW + bC * 4]);

    float acc[2][8][4];
#pragma unroll
    for (int i = 0; i < 2; i++)
#pragma unroll
        for (int j = 0; j < 8; j++)
#pragma unroll
            for (int l = 0; l < 4; l++) acc[i][j][l] = 0.0f;

    const int KT = K / TBK;

#define T_ISSUE(kt, sa, sb)                                                  \
    do {                                                                     \
        const float* ag = Ag + (size_t)(kt) * TBK;                           \
        const float* bg = Bg + (size_t)(kt) * TBK * N;                       \
        cp16f((sa), ag);                                                     \
        cp16f((sa) + 16, ag + 4);                                            \
        cp16f((sb), bg);                                                     \
        cp16f((sb) + 8 * B_STW * 4, bg + (size_t)8 * N);                     \
        asm volatile("cp.async.commit_group;");                              \
    } while (0)

    T_ISSUE(0, sa0, sb0);

    for (int kt = 0; kt < KT; kt++) {
        const int buf = kt & 1;
        if (kt + 1 < KT) {
            if (buf == 0) T_ISSUE(kt + 1, sa1, sb1);
            else          T_ISSUE(kt + 1, sa0, sb0);
            asm volatile("cp.async.wait_group 1;");
        } else {
            asm volatile("cp.async.wait_group 0;");
        }
        __syncthreads();

        const float* cA = As[buf];
        const float* cB = Bs[buf];

#pragma unroll
        for (int ks = 0; ks < 2; ks++) {
            const int k8 = ks * 8;
            uint32_t aH[2][4], aL[2][4];
#pragma unroll
            for (int mt = 0; mt < 2; mt++) {
                const int m = wm * 32 + mt * 16 + gid;
                split_tf32(cA[m * A_STW + k8 + tid4],           aH[mt][0], aL[mt][0]);
                split_tf32(cA[(m + 8) * A_STW + k8 + tid4],     aH[mt][1], aL[mt][1]);
                split_tf32(cA[m * A_STW + k8 + tid4 + 4],       aH[mt][2], aL[mt][2]);
                split_tf32(cA[(m + 8) * A_STW + k8 + tid4 + 4], aH[mt][3], aL[mt][3]);
            }
#pragma unroll
            for (int nt = 0; nt < 8; nt++) {
                const int n = wn * 64 + nt * 8 + gid;
                uint32_t bH0, bH1, bL0, bL1;
                split_tf32(cB[(k8 + tid4) * B_STW + n],     bH0, bL0);
                split_tf32(cB[(k8 + tid4 + 4) * B_STW + n], bH1, bL1);
#pragma unroll
                for (int mt = 0; mt < 2; mt++) {
                    mma_tf32(acc[mt][nt], aH[mt], bH0, bH1);
                    mma_tf32(acc[mt][nt], aH[mt], bL0, bL1);
                    mma_tf32(acc[mt][nt], aL[mt], bH0, bH1);
                }
            }
        }
        __syncthreads();
    }
#undef T_ISSUE

    // Epilogue: bias + optional gelu
#pragma unroll
    for (int mt = 0; mt < 2; mt++) {
        const int r0 = bm + wm * 32 + mt * 16 + gid;
#pragma unroll
        for (int nt = 0; nt < 8; nt++) {
            const int col = bn + wn * 64 + nt * 8 + tid4 * 2;
            const float bx = __ldg(&bias[col]);
            const float by = __ldg(&bias[col + 1]);
            float v0 = acc[mt][nt][0] + bx;
            float v1 = acc[mt][nt][1] + by;
            float v2 = acc[mt][nt][2] + bx;
            float v3 = acc[mt][nt][3] + by;
            if (doGelu) {
                v0 = gelu_exact(v0); v1 = gelu_exact(v1);
                v2 = gelu_exact(v2); v3 = gelu_exact(v3);
            }
            *(float2*)(C + (size_t)r0 * N + col)       = make_float2(v0, v1);
            *(float2*)(C + (size_t)(r0 + 8) * N + col) = make_float2(v2, v3);
        }
    }
}

// ---------------------------------------------------------------------------
// Split-bf16 tensor-core GEMM for GEMM3/GEMM4 (proven R3 kernel, unchanged).
// ---------------------------------------------------------------------------
#define GBK 32
#define A_ST 40
#define B_ST 136
#define A_MAT (128 * A_ST)
#define B_MAT (GBK * B_ST)
#define SMEM_SPLIT_BYTES ((2 * 2 * A_MAT + 2 * 2 * B_MAT) * 2)

__device__ __forceinline__ void ldsm_x4(uint32_t* r, uint32_t addr) {
    asm volatile("ldmatrix.sync.aligned.m8n8.x4.shared.b16 {%0,%1,%2,%3}, [%4];"
                 : "=r"(r[0]), "=r"(r[1]), "=r"(r[2]), "=r"(r[3]) : "r"(addr));
}
__device__ __forceinline__ void ldsm_x4_t(uint32_t* r, uint32_t addr) {
    asm volatile("ldmatrix.sync.aligned.m8n8.x4.trans.shared.b16 {%0,%1,%2,%3}, [%4];"
                 : "=r"(r[0]), "=r"(r[1]), "=r"(r[2]), "=r"(r[3]) : "r"(addr));
}
__device__ __forceinline__ void mma_bf16(float* d, const uint32_t* a,
                                         uint32_t b0, uint32_t b1) {
    asm volatile(
        "mma.sync.aligned.m16n8k16.row.col.f32.bf16.bf16.f32 "
        "{%0,%1,%2,%3},{%4,%5,%6,%7},{%8,%9},{%0,%1,%2,%3};"
        : "+f"(d[0]), "+f"(d[1]), "+f"(d[2]), "+f"(d[3])
        : "r"(a[0]), "r"(a[1]), "r"(a[2]), "r"(a[3]), "r"(b0), "r"(b1));
}
__device__ __forceinline__ void cp16(uint32_t saddr, const void* g) {
    asm volatile("cp.async.cg.shared.global [%0], [%1], 16;"
                 :: "r"(saddr), "l"(g));
}

__global__ void __launch_bounds__(256, 2)
split_gemm_kernel(const __nv_bfloat16* __restrict__ Ahi,
                  const __nv_bfloat16* __restrict__ Alo,
                  const __nv_bfloat16* __restrict__ Bhi,
                  const __nv_bfloat16* __restrict__ Blo,
                  const float* __restrict__ bias,
                  float* __restrict__ outF,
                  __nv_bfloat16* __restrict__ outHi,
                  __nv_bfloat16* __restrict__ outLo,
                  int M, int N, int K, int mode)
{
    extern __shared__ __nv_bfloat16 smem[];
    __nv_bfloat16* sA = smem;
    __nv_bfloat16* sB = smem + 4 * A_MAT;

    const int tid  = threadIdx.x;
    const int lane = tid & 31;
    const int warp = tid >> 5;
    const int wm   = warp >> 1;
    const int wn   = warp & 1;
    const int bm   = blockIdx.y * 128;
    const int bn   = blockIdx.x * 128;

    const int arow = tid >> 2;
    const int acol = (tid & 3) * 8;
    const int brow = tid >> 4;
    const int bcol = (tid & 15) * 8;

    const __nv_bfloat16* AgH = Ahi + (size_t)(bm + arow) * K + acol;
    const __nv_bfloat16* AgL = Alo + (size_t)(bm + arow) * K + acol;
    const __nv_bfloat16* BgH = Bhi + (size_t)brow * N + bn + bcol;
    const __nv_bfloat16* BgL = Blo + (size_t)brow * N + bn + bcol;

    const uint32_t saBase = (uint32_t)__cvta_generic_to_shared(
        &sA[arow * A_ST + acol]);
    const uint32_t sbBase = (uint32_t)__cvta_generic_to_shared(
        &sB[brow * B_ST + bcol]);

    float acc[2][8][4];
#pragma unroll
    for (int i = 0; i < 2; i++)
#pragma unroll
        for (int j = 0; j < 8; j++)
#pragma unroll
            for (int l = 0; l < 4; l++) acc[i][j][l] = 0.0f;

    const int KT = K / GBK;

#define ISSUE_TILE(kt, buf)                                                   \
    do {                                                                      \
        const size_t ka = (size_t)(kt) * GBK;                                 \
        const size_t kb = (size_t)(kt) * GBK * N;                             \
        const uint32_t aOff = (buf) * (2 * A_MAT * 2);                        \
        const uint32_t bOff = (buf) * (2 * B_MAT * 2);                        \
        cp16(saBase + aOff, AgH + ka);                                        \
        cp16(saBase + aOff + 64 * A_ST * 2, AgH + ka + (size_t)64 * K);       \
        cp16(saBase + aOff + A_MAT * 2, AgL + ka);                            \
        cp16(saBase + aOff + A_MAT * 2 + 64 * A_ST * 2,                       \
             AgL + ka + (size_t)64 * K);                                      \
        cp16(sbBase + bOff, BgH + kb);                                        \
        cp16(sbBase + bOff + 16 * B_ST * 2, BgH + kb + (size_t)16 * N);       \
        cp16(sbBase + bOff + B_MAT * 2, BgL + kb);                            \
        cp16(sbBase + bOff + B_MAT * 2 + 16 * B_ST * 2,                       \
             BgL + kb + (size_t)16 * N);                                      \
        asm volatile("cp.async.commit_group;");                               \
    } while (0)

    ISSUE_TILE(0, 0);

    for (int kt = 0; kt < KT; kt++) {
        const int buf = kt & 1;
        if (kt + 1 < KT) {
            ISSUE_TILE(kt + 1, buf ^ 1);
            asm volatile("cp.async.wait_group 1;");
        } else {
            asm volatile("cp.async.wait_group 0;");
        }
        __syncthreads();

        const __nv_bfloat16* cAhi = sA + buf * 2 * A_MAT;
        const __nv_bfloat16* cAlo = cAhi + A_MAT;
        const __nv_bfloat16* cBhi = sB + buf * 2 * B_MAT;
        const __nv_bfloat16* cBlo = cBhi + B_MAT;

#pragma unroll
        for (int ks = 0; ks < 2; ks++) {
            uint32_t aH[2][4], aL[2][4];
#pragma unroll
            for (int mt = 0; mt < 2; mt++) {
                int row = wm * 32 + mt * 16 + (lane & 15);
                int col = ks * 16 + (lane >> 4) * 8;
                ldsm_x4(aH[mt], (uint32_t)__cvta_generic_to_shared(
                                    &cAhi[row * A_ST + col]));
                ldsm_x4(aL[mt], (uint32_t)__cvta_generic_to_shared(
                                    &cAlo[row * A_ST + col]));
            }
#pragma unroll
            for (int nt = 0; nt < 4; nt++) {
                int krow = ks * 16 + (lane & 15);
                int ncol = wn * 64 + nt * 16 + (lane >> 4) * 8;
                uint32_t bH[4], bL[4];
                ldsm_x4_t(bH, (uint32_t)__cvta_generic_to_shared(
                                  &cBhi[krow * B_ST + ncol]));
                ldsm_x4_t(bL, (uint32_t)__cvta_generic_to_shared(
                                  &cBlo[krow * B_ST + ncol]));
#pragma unroll
                for (int mt = 0; mt < 2; mt++) {
                    float* a0 = acc[mt][nt * 2 + 0];
                    float* a1 = acc[mt][nt * 2 + 1];
                    mma_bf16(a0, aH[mt], bH[0], bH[1]);
                    mma_bf16(a1, aH[mt], bH[2], bH[3]);
                    mma_bf16(a0, aH[mt], bL[0], bL[1]);
                    mma_bf16(a1, aH[mt], bL[2], bL[3]);
                    mma_bf16(a0, aL[mt], bH[0], bH[1]);
                    mma_bf16(a1, aL[mt], bH[2], bH[3]);
                }
            }
        }
        __syncthreads();
    }
#undef ISSUE_TILE

#pragma unroll
    for (int mt = 0; mt < 2; mt++) {
        const int r0 = bm + wm * 32 + mt * 16 + (lane >> 2);
#pragma unroll
        for (int nt8 = 0; nt8 < 8; nt8++) {
            const int col = bn + wn * 64 + nt8 * 8 + (lane & 3) * 2;
            const float bx = __ldg(&bias[col]);
            const float by = __ldg(&bias[col + 1]);
            float v0 = acc[mt][nt8][0] + bx;
            float v1 = acc[mt][nt8][1] + by;
            float v2 = acc[mt][nt8][2] + bx;
            float v3 = acc[mt][nt8][3] + by;
            if (mode == 1) {
                v0 = gelu_exact(v0); v1 = gelu_exact(v1);
                v2 = gelu_exact(v2); v3 = gelu_exact(v3);
                __nv_bfloat16 h0 = __float2bfloat16_rn(v0);
                __nv_bfloat16 h1 = __float2bfloat16_rn(v1);
                __nv_bfloat16 h2 = __float2bfloat16_rn(v2);
                __nv_bfloat16 h3v = __float2bfloat16_rn(v3);
                __nv_bfloat16 l0 = __float2bfloat16_rn(v0 - __bfloat162float(h0));
                __nv_bfloat16 l1 = __float2bfloat16_rn(v1 - __bfloat162float(h1));
                __nv_bfloat16 l2 = __float2bfloat16_rn(v2 - __bfloat162float(h2));
                __nv_bfloat16 l3 = __float2bfloat16_rn(v3 - __bfloat162float(h3v));
                *(__nv_bfloat162*)(outHi + (size_t)r0 * N + col) =
                    __nv_bfloat162(h0, h1);
                *(__nv_bfloat162*)(outHi + (size_t)(r0 + 8) * N + col) =
                    __nv_bfloat162(h2, h3v);
                *(__nv_bfloat162*)(outLo + (size_t)r0 * N + col) =
                    __nv_bfloat162(l0, l1);
                *(__nv_bfloat162*)(outLo + (size_t)(r0 + 8) * N + col) =
                    __nv_bfloat162(l2, l3);
            } else {
                *(float2*)(outF + (size_t)r0 * N + col)       = make_float2(v0, v1);
                *(float2*)(outF + (size_t)(r0 + 8) * N + col) = make_float2(v2, v3);
            }
        }
    }
}

// ---------------------------------------------------------------------------
// e_sq, counts init
// ---------------------------------------------------------------------------
__global__ void esq_kernel(const float* __restrict__ cb, float* __restrict__ esq)
{
    int idx = blockIdx.x * blockDim.x + threadIdx.x;
    if (idx >= NC * NK) return;
    const float* e = cb + (size_t)idx * DPC;
    float s = 0.0f;
#pragma unroll
    for (int d = 0; d < DPC; d++) s += e[d] * e[d];
    esq[idx] = s;
}

__global__ void zero_counts_kernel(int* __restrict__ counts)
{
    int idx = blockIdx.x * blockDim.x + threadIdx.x;
    if (idx < NC * NK) counts[idx] = 0;
}

// ---------------------------------------------------------------------------
// VQ: fp32 argmin (exact), z_q emitted as split bf16 (hi, lo)
// ---------------------------------------------------------------------------
#define VQ_TB 128
#define VQ_KC 128

__global__ void __launch_bounds__(VQ_TB)
vq_kernel(const float* __restrict__ z, const float* __restrict__ codebooks,
          const float* __restrict__ esq,
          __nv_bfloat16* __restrict__ zqHi, __nv_bfloat16* __restrict__ zqLo,
          float* __restrict__ out_idx, float* __restrict__ partials,
          int* __restrict__ counts)
{
    __shared__ float E[VQ_KC][DPC];
    __shared__ float Esq_s[VQ_KC];
    __shared__ float red[VQ_TB];

    const int c   = blockIdx.y;
    const int tid = threadIdx.x;
    const int t   = blockIdx.x * VQ_TB + tid;

    float zr[DPC];
    {
        const float4* zp = (const float4*)(z + (size_t)t * D_E + c * DPC);
#pragma unroll
        for (int q = 0; q < DPC / 4; q++) {
            float4 v = zp[q];
            zr[4 * q + 0] = v.x; zr[4 * q + 1] = v.y;
            zr[4 * q + 2] = v.z; zr[4 * q + 3] = v.w;
        }
    }
    float zsq = 0.0f;
#pragma unroll
    for (int d = 0; d < DPC; d++) zsq = fmaf(zr[d], zr[d], zsq);

    const float* cb = codebooks + (size_t)c * NK * DPC;

    float best = 3.4e38f;
    int   bidx = 0;

    for (int k0 = 0; k0 < NK; k0 += VQ_KC) {
        for (int i = tid; i < VQ_KC * (DPC / 4); i += VQ_TB) {
            int row = i >> 4;
            int q   = i & 15;
            float4 v = *(const float4*)(cb + (size_t)(k0 + row) * DPC + q * 4);
            *(float4*)&E[row][q * 4] = v;
        }
        Esq_s[tid] = esq[c * NK + k0 + tid];
        __syncthreads();

        for (int j = 0; j < VQ_KC; j++) {
            float d0 = 0.f, d1 = 0.f, d2 = 0.f, d3 = 0.f;
#pragma unroll
            for (int d = 0; d < DPC; d += 4) {
                d0 = fmaf(zr[d + 0], E[j][d + 0], d0);
                d1 = fmaf(zr[d + 1], E[j][d + 1], d1);
                d2 = fmaf(zr[d + 2], E[j][d + 2], d2);
                d3 = fmaf(zr[d + 3], E[j][d + 3], d3);
            }
            float dot  = (d0 + d1) + (d2 + d3);
            float dist = zsq - 2.0f * dot + Esq_s[j];
            if (dist < best) { best = dist; bidx = k0 + j; }
        }
        __syncthreads();
    }

    const float* e = cb + (size_t)bidx * DPC;
    __nv_bfloat16* zh = zqHi + (size_t)t * D_E + c * DPC;
    __nv_bfloat16* zl = zqLo + (size_t)t * D_E + c * DPC;
    float cs = 0.0f;
#pragma unroll
    for (int q = 0; q < DPC / 4; q++) {
        float4 ev = *(const float4*)(e + q * 4);
        __nv_bfloat16 hx = __float2bfloat16_rn(ev.x);
        __nv_bfloat16 hy = __float2bfloat16_rn(ev.y);
        __nv_bfloat16 hz = __float2bfloat16_rn(ev.z);
        __nv_bfloat16 hw = __float2bfloat16_rn(ev.w);
        *(__nv_bfloat162*)(zh + 4 * q)     = __nv_bfloat162(hx, hy);
        *(__nv_bfloat162*)(zh + 4 * q + 2) = __nv_bfloat162(hz, hw);
        *(__nv_bfloat162*)(zl + 4 * q) = __nv_bfloat162(
            __float2bfloat16_rn(ev.x - __bfloat162float(hx)),
            __float2bfloat16_rn(ev.y - __bfloat162float(hy)));
        *(__nv_bfloat162*)(zl + 4 * q + 2) = __nv_bfloat162(
            __float2bfloat16_rn(ev.z - __bfloat162float(hz)),
            __float2bfloat16_rn(ev.w - __bfloat162float(hw)));
        float dx = zr[4 * q + 0] - ev.x;
        float dy = zr[4 * q + 1] - ev.y;
        float dz = zr[4 * q + 2] - ev.z;
        float dw = zr[4 * q + 3] - ev.w;
        cs += dx * dx + dy * dy + dz * dz + dw * dw;
    }

    atomicAdd(&counts[c * NK + bidx], 1);
    out_idx[(size_t)t * NC + c] = (float)bidx;

    red[tid] = cs;
    __syncthreads();
    for (int s = VQ_TB / 2; s > 0; s >>= 1) {
        if (tid < s) red[tid] += red[tid + s];
        __syncthreads();
    }
    if (tid == 0) partials[blockIdx.y * gridDim.x + blockIdx.x] = red[0];
}

// ---------------------------------------------------------------------------
// Finalize scalars
// ---------------------------------------------------------------------------
__global__ void __launch_bounds__(256)
finalize_kernel(const float* __restrict__ partials, int npart,
                const int* __restrict__ counts, float* __restrict__ out_scalars)
{
    __shared__ float sm[256];
    const int tid = threadIdx.x;

    float v = (tid < npart) ? partials[tid] : 0.0f;
    sm[tid] = v;
    __syncthreads();
    for (int s = 128; s > 0; s >>= 1) {
        if (tid < s) sm[tid] += sm[tid + s];
        __syncthreads();
    }
    if (tid == 0) {
        float commitment = 0.25f * sm[0] / (float)(T_TOKENS * D_E);
        out_scalars[0] = commitment;
        out_scalars[1] = commitment;
    }

    float ent_acc = 0.0f;
    for (int c = 0; c < NC; c++) {
        float s = 0.0f;
        for (int k = tid; k < NK; k += 256) {
            float p = (float)counts[c * NK + k] * (1.0f / 8192.0f);
            s -= p * logf(p + 1e-10f);
        }
        __syncthreads();
        sm[tid] = s;
        __syncthreads();
        for (int st = 128; st > 0; st >>= 1) {
            if (tid < st) sm[tid] += sm[tid + st];
            __syncthreads();
        }
        if (tid == 0) ent_acc += sm[0];
        __syncthreads();
    }
    if (tid == 0) out_scalars[2] = ent_acc * 0.25f;
}

// ---------------------------------------------------------------------------
// Host launcher. Inputs: x, W1, b1, W2, b2, codebooks, W3, b3, W4, b4
// ---------------------------------------------------------------------------
extern "C" void kernel_launch(void* const* d_in, const int* in_sizes, int n_in,
                              void* d_out, int out_size)
{
    const float* x   = (const float*)d_in[0];
    const float* W1  = (const float*)d_in[1];
    const float* b1  = (const float*)d_in[2];
    const float* W2  = (const float*)d_in[3];
    const float* b2  = (const float*)d_in[4];
    const float* cb  = (const float*)d_in[5];
    const float* W3  = (const float*)d_in[6];
    const float* b3  = (const float*)d_in[7];
    const float* W4  = (const float*)d_in[8];
    const float* b4  = (const float*)d_in[9];

    float* out = (float*)d_out;

    float *h1, *z, *esq, *part;
    __nv_bfloat16 *zqH, *zqL, *h3H, *h3L, *w3H, *w3L, *w4H, *w4L;
    int* counts;
    cudaGetSymbolAddress((void**)&h1,  g_h1);
    cudaGetSymbolAddress((void**)&z,   g_z);
    cudaGetSymbolAddress((void**)&zqH, g_zq_hi);
    cudaGetSymbolAddress((void**)&zqL, g_zq_lo);
    cudaGetSymbolAddress((void**)&h3H, g_h3_hi);
    cudaGetSymbolAddress((void**)&h3L, g_h3_lo);
    cudaGetSymbolAddress((void**)&w3H, g_w3_hi);
    cudaGetSymbolAddress((void**)&w3L, g_w3_lo);
    cudaGetSymbolAddress((void**)&w4H, g_w4_hi);
    cudaGetSymbolAddress((void**)&w4L, g_w4_lo);
    cudaGetSymbolAddress((void**)&esq, g_esq);
    cudaGetSymbolAddress((void**)&part, g_part);
    cudaGetSymbolAddress((void**)&counts, g_counts);

    cudaFuncSetAttribute(split_gemm_kernel,
                         cudaFuncAttributeMaxDynamicSharedMemorySize,
                         SMEM_SPLIT_BYTES);

    // 0) weight split conversions (bf16 hi/lo for GEMM3/4)
    {
        int n3 = D_E * D_H3;
        int n4 = D_H3 * D_OUT;
        f2bf_split_kernel<<<(n3 / 4 + 255) / 256, 256>>>(W3, w3H, w3L, n3);
        f2bf_split_kernel<<<(n4 / 4 + 255) / 256, 256>>>(W4, w4H, w4L, n4);
    }

    // 1) h1 = gelu(x @ W1 + b1)   3xTF32 (near-fp32 exact)
    tf32_gemm_kernel<<<dim3(D_H1 / 128, T_TOKENS / 128), 256>>>(
        x, W1, b1, h1, T_TOKENS, D_H1, D_IN, 1);

    // 2) z = h1 @ W2 + b2         3xTF32 (near-fp32 exact)
    tf32_gemm_kernel<<<dim3(D_E / 128, T_TOKENS / 128), 256>>>(
        h1, W2, b2, z, T_TOKENS, D_E, D_H1, 0);

    // 3) code norms + zero counts
    esq_kernel<<<(NC * NK + 255) / 256, 256>>>(cb, esq);
    zero_counts_kernel<<<(NC * NK + 255) / 256, 256>>>(counts);

    // 4) VQ (fp32 argmin, split-bf16 z_q)
    vq_kernel<<<dim3(T_TOKENS / VQ_TB, NC), VQ_TB>>>(
        z, cb, esq, zqH, zqL, out + XVQ_ELEMS, part, counts);

    // 5) scalars
    finalize_kernel<<<1, 256>>>(part, (T_TOKENS / VQ_TB) * NC, counts,
                                out + XVQ_ELEMS + IDX_ELEMS);

    // 6) h3 = gelu(zq @ W3 + b3)  split-bf16 tensor cores -> split h3
    split_gemm_kernel<<<dim3(D_H3 / 128, T_TOKENS / 128), 256,
                        SMEM_SPLIT_BYTES>>>(
        zqH, zqL, w3H, w3L, b3, nullptr, h3H, h3L,
        T_TOKENS, D_H3, D_E, 1);

    // 7) x_vq = h3 @ W4 + b4 -> out  split-bf16 tensor cores
    split_gemm_kernel<<<dim3(D_OUT / 128, T_TOKENS / 128), 256,
                        SMEM_SPLIT_BYTES>>>(
        h3H, h3L, w4H, w4L, b4, out, nullptr, nullptr,
        T_TOKENS, D_OUT, D_H3, 0);
}

// round 7
// speedup vs baseline: 5.0599x; 1.7896x over previous
#include <cuda_runtime.h>
#include <cuda_bf16.h>
#include <cuda_fp16.h>
#include <math.h>
#include <stdint.h>

// ---------------------------------------------------------------------------
// Constants: T=8192; D_IN=1152, 4D_IN=4608, D_E=256, C=4, K=2048, dpc=64,
// H=4096, 4H=16384.
// Output (fp32): x_vq [8192*4096] | idx [8192*4] | total, commitment, entropy
// ---------------------------------------------------------------------------
#define T_TOKENS 8192
#define D_IN     1152
#define D_H1     4608
#define D_E      256
#define NC       4
#define NK       2048
#define DPC      64
#define D_H3     16384
#define D_OUT    4096

#define XVQ_ELEMS   (T_TOKENS * D_OUT)
#define IDX_ELEMS   (T_TOKENS * NC)

// Scratch
__device__ float          g_h1[(size_t)T_TOKENS * D_H1];
__device__ float          g_z [(size_t)T_TOKENS * D_E];
__device__ __nv_bfloat16  g_zq_hi[(size_t)T_TOKENS * D_E];
__device__ __nv_bfloat16  g_zq_lo[(size_t)T_TOKENS * D_E];
__device__ __half         g_h3_h[(size_t)T_TOKENS * D_H3];   // fp16 h3
__device__ __nv_bfloat16  g_w3_hi[(size_t)D_E * D_H3];
__device__ __nv_bfloat16  g_w3_lo[(size_t)D_E * D_H3];
__device__ __half         g_w4_h[(size_t)D_H3 * D_OUT];      // fp16 W4
__device__ float g_esq[NC * NK];
__device__ int   g_counts[NC * NK];
__device__ float g_part[256];

__device__ __forceinline__ float gelu_exact(float x) {
    return 0.5f * x * (1.0f + erff(x * 0.70710678118654752440f));
}

// ---------------------------------------------------------------------------
// fp32 -> (bf16 hi, bf16 lo) split conversion (W3)
// ---------------------------------------------------------------------------
__global__ void f2bf_split_kernel(const float* __restrict__ in,
                                  __nv_bfloat16* __restrict__ hi,
                                  __nv_bfloat16* __restrict__ lo, int n)
{
    int i = (blockIdx.x * blockDim.x + threadIdx.x) * 4;
    if (i >= n) return;
    float4 v = *(const float4*)(in + i);
    __nv_bfloat16 hx = __float2bfloat16_rn(v.x);
    __nv_bfloat16 hy = __float2bfloat16_rn(v.y);
    __nv_bfloat16 hz = __float2bfloat16_rn(v.z);
    __nv_bfloat16 hw = __float2bfloat16_rn(v.w);
    *(__nv_bfloat162*)(hi + i)     = __nv_bfloat162(hx, hy);
    *(__nv_bfloat162*)(hi + i + 2) = __nv_bfloat162(hz, hw);
    *(__nv_bfloat162*)(lo + i) = __nv_bfloat162(
        __float2bfloat16_rn(v.x - __bfloat162float(hx)),
        __float2bfloat16_rn(v.y - __bfloat162float(hy)));
    *(__nv_bfloat162*)(lo + i + 2) = __nv_bfloat162(
        __float2bfloat16_rn(v.z - __bfloat162float(hz)),
        __float2bfloat16_rn(v.w - __bfloat162float(hw)));
}

// ---------------------------------------------------------------------------
// fp32 -> fp16 conversion (W4)
// ---------------------------------------------------------------------------
__global__ void f2h_kernel(const float* __restrict__ in,
                           __half* __restrict__ out, int n)
{
    int i = (blockIdx.x * blockDim.x + threadIdx.x) * 4;
    if (i >= n) return;
    float4 v = *(const float4*)(in + i);
    *(__half2*)(out + i)     = __floats2half2_rn(v.x, v.y);
    *(__half2*)(out + i + 2) = __floats2half2_rn(v.z, v.w);
}

// ---------------------------------------------------------------------------
// 3xTF32 split GEMM (GEMM1/GEMM2): near-fp32 precision on tensor cores.
// ---------------------------------------------------------------------------
#define TBK 16
#define A_STW 20
#define B_STW 136

__device__ __forceinline__ uint32_t f2tf32(float v) {
    uint32_t r;
    asm("cvt.rna.tf32.f32 %0, %1;" : "=r"(r) : "f"(v));
    return r;
}
__device__ __forceinline__ void split_tf32(float v, uint32_t& h, uint32_t& l) {
    h = f2tf32(v);
    l = f2tf32(v - __uint_as_float(h));
}
__device__ __forceinline__ void mma_tf32(float* d, const uint32_t* a,
                                         uint32_t b0, uint32_t b1) {
    asm volatile(
        "mma.sync.aligned.m16n8k8.row.col.f32.tf32.tf32.f32 "
        "{%0,%1,%2,%3},{%4,%5,%6,%7},{%8,%9},{%0,%1,%2,%3};"
        : "+f"(d[0]), "+f"(d[1]), "+f"(d[2]), "+f"(d[3])
        : "r"(a[0]), "r"(a[1]), "r"(a[2]), "r"(a[3]), "r"(b0), "r"(b1));
}
__device__ __forceinline__ void cp16f(uint32_t saddr, const void* g) {
    asm volatile("cp.async.cg.shared.global [%0], [%1], 16;"
                 :: "r"(saddr), "l"(g));
}

__global__ void __launch_bounds__(256, 2)
tf32_gemm_kernel(const float* __restrict__ A, const float* __restrict__ B,
                 const float* __restrict__ bias, float* __restrict__ C,
                 int M, int N, int K, int doGelu)
{
    __shared__ float As[2][128 * A_STW];
    __shared__ float Bs[2][TBK * B_STW];

    const int tid  = threadIdx.x;
    const int lane = tid & 31;
    const int warp = tid >> 5;
    const int wm   = warp >> 1;
    const int wn   = warp & 1;
    const int gid  = lane >> 2;
    const int tid4 = lane & 3;
    const int bm   = blockIdx.y * 128;
    const int bn   = blockIdx.x * 128;

    const int aRow = tid >> 1;
    const int aQ   = (tid & 1) * 2;
    const int bK   = tid >> 5;
    const int bC   = tid & 31;

    const float* Ag = A + (size_t)(bm + aRow) * K + aQ * 4;
    const float* Bg = B + (size_t)bK * N + bn + bC * 4;

    const uint32_t sa0 = (uint32_t)__cvta_generic_to_shared(
        &As[0][aRow * A_STW + aQ * 4]);
    const uint32_t sa1 = (uint32_t)__cvta_generic_to_shared(
        &As[1][aRow * A_STW + aQ * 4]);
    const uint32_t sb0 = (uint32_t)__cvta_generic_to_shared(
        &Bs[0][bK * B_STW + bC * 4]);
    const uint32_t sb1 = (uint32_t)__cvta_generic_to_shared(
        &Bs[1][bK * B_STW + bC * 4]);

    float acc[2][8][4];
#pragma unroll
    for (int i = 0; i < 2; i++)
#pragma unroll
        for (int j = 0; j < 8; j++)
#pragma unroll
            for (int l = 0; l < 4; l++) acc[i][j][l] = 0.0f;

    const int KT = K / TBK;

#define T_ISSUE(kt, sa, sb)                                                  \
    do {                                                                     \
        const float* ag = Ag + (size_t)(kt) * TBK;                           \
        const float* bg = Bg + (size_t)(kt) * TBK * N;                       \
        cp16f((sa), ag);                                                     \
        cp16f((sa) + 16, ag + 4);                                            \
        cp16f((sb), bg);                                                     \
        cp16f((sb) + 8 * B_STW * 4, bg + (size_t)8 * N);                     \
        asm volatile("cp.async.commit_group;");                              \
    } while (0)

    T_ISSUE(0, sa0, sb0);

    for (int kt = 0; kt < KT; kt++) {
        const int buf = kt & 1;
        if (kt + 1 < KT) {
            if (buf == 0) T_ISSUE(kt + 1, sa1, sb1);
            else          T_ISSUE(kt + 1, sa0, sb0);
            asm volatile("cp.async.wait_group 1;");
        } else {
            asm volatile("cp.async.wait_group 0;");
        }
        __syncthreads();

        const float* cA = As[buf];
        const float* cB = Bs[buf];

#pragma unroll
        for (int ks = 0; ks < 2; ks++) {
            const int k8 = ks * 8;
            uint32_t aH[2][4], aL[2][4];
#pragma unroll
            for (int mt = 0; mt < 2; mt++) {
                const int m = wm * 32 + mt * 16 + gid;
                split_tf32(cA[m * A_STW + k8 + tid4],           aH[mt][0], aL[mt][0]);
                split_tf32(cA[(m + 8) * A_STW + k8 + tid4],     aH[mt][1], aL[mt][1]);
                split_tf32(cA[m * A_STW + k8 + tid4 + 4],       aH[mt][2], aL[mt][2]);
                split_tf32(cA[(m + 8) * A_STW + k8 + tid4 + 4], aH[mt][3], aL[mt][3]);
            }
#pragma unroll
            for (int nt = 0; nt < 8; nt++) {
                const int n = wn * 64 + nt * 8 + gid;
                uint32_t bH0, bH1, bL0, bL1;
                split_tf32(cB[(k8 + tid4) * B_STW + n],     bH0, bL0);
                split_tf32(cB[(k8 + tid4 + 4) * B_STW + n], bH1, bL1);
#pragma unroll
                for (int mt = 0; mt < 2; mt++) {
                    mma_tf32(acc[mt][nt], aH[mt], bH0, bH1);
                    mma_tf32(acc[mt][nt], aH[mt], bL0, bL1);
                    mma_tf32(acc[mt][nt], aL[mt], bH0, bH1);
                }
            }
        }
        __syncthreads();
    }
#undef T_ISSUE

#pragma unroll
    for (int mt = 0; mt < 2; mt++) {
        const int r0 = bm + wm * 32 + mt * 16 + gid;
#pragma unroll
        for (int nt = 0; nt < 8; nt++) {
            const int col = bn + wn * 64 + nt * 8 + tid4 * 2;
            const float bx = __ldg(&bias[col]);
            const float by = __ldg(&bias[col + 1]);
            float v0 = acc[mt][nt][0] + bx;
            float v1 = acc[mt][nt][1] + by;
            float v2 = acc[mt][nt][2] + bx;
            float v3 = acc[mt][nt][3] + by;
            if (doGelu) {
                v0 = gelu_exact(v0); v1 = gelu_exact(v1);
                v2 = gelu_exact(v2); v3 = gelu_exact(v3);
            }
            *(float2*)(C + (size_t)r0 * N + col)       = make_float2(v0, v1);
            *(float2*)(C + (size_t)(r0 + 8) * N + col) = make_float2(v2, v3);
        }
    }
}

// ---------------------------------------------------------------------------
// Shared smem-layout constants for the 16-bit GEMMs
// ---------------------------------------------------------------------------
#define GBK 32
#define A_ST 40
#define B_ST 136
#define A_MAT (128 * A_ST)
#define B_MAT (GBK * B_ST)
#define SMEM_SPLIT_BYTES ((2 * 2 * A_MAT + 2 * 2 * B_MAT) * 2)

__device__ __forceinline__ void ldsm_x4(uint32_t* r, uint32_t addr) {
    asm volatile("ldmatrix.sync.aligned.m8n8.x4.shared.b16 {%0,%1,%2,%3}, [%4];"
                 : "=r"(r[0]), "=r"(r[1]), "=r"(r[2]), "=r"(r[3]) : "r"(addr));
}
__device__ __forceinline__ void ldsm_x4_t(uint32_t* r, uint32_t addr) {
    asm volatile("ldmatrix.sync.aligned.m8n8.x4.trans.shared.b16 {%0,%1,%2,%3}, [%4];"
                 : "=r"(r[0]), "=r"(r[1]), "=r"(r[2]), "=r"(r[3]) : "r"(addr));
}
__device__ __forceinline__ void mma_bf16(float* d, const uint32_t* a,
                                         uint32_t b0, uint32_t b1) {
    asm volatile(
        "mma.sync.aligned.m16n8k16.row.col.f32.bf16.bf16.f32 "
        "{%0,%1,%2,%3},{%4,%5,%6,%7},{%8,%9},{%0,%1,%2,%3};"
        : "+f"(d[0]), "+f"(d[1]), "+f"(d[2]), "+f"(d[3])
        : "r"(a[0]), "r"(a[1]), "r"(a[2]), "r"(a[3]), "r"(b0), "r"(b1));
}
__device__ __forceinline__ void mma_f16(float* d, const uint32_t* a,
                                        uint32_t b0, uint32_t b1) {
    asm volatile(
        "mma.sync.aligned.m16n8k16.row.col.f32.f16.f16.f32 "
        "{%0,%1,%2,%3},{%4,%5,%6,%7},{%8,%9},{%0,%1,%2,%3};"
        : "+f"(d[0]), "+f"(d[1]), "+f"(d[2]), "+f"(d[3])
        : "r"(a[0]), "r"(a[1]), "r"(a[2]), "r"(a[3]), "r"(b0), "r"(b1));
}
__device__ __forceinline__ void cp16(uint32_t saddr, const void* g) {
    asm volatile("cp.async.cg.shared.global [%0], [%1], 16;"
                 :: "r"(saddr), "l"(g));
}

// ---------------------------------------------------------------------------
// GEMM3: split-bf16 3-term (accurate), epilogue gelu -> fp16 h3.
// ---------------------------------------------------------------------------
__global__ void __launch_bounds__(256, 2)
split_gemm3_kernel(const __nv_bfloat16* __restrict__ Ahi,
                   const __nv_bfloat16* __restrict__ Alo,
                   const __nv_bfloat16* __restrict__ Bhi,
                   const __nv_bfloat16* __restrict__ Blo,
                   const float* __restrict__ bias,
                   __half* __restrict__ outH,
                   int M, int N, int K)
{
    extern __shared__ __nv_bfloat16 smem[];
    __nv_bfloat16* sA = smem;
    __nv_bfloat16* sB = smem + 4 * A_MAT;

    const int tid  = threadIdx.x;
    const int lane = tid & 31;
    const int warp = tid >> 5;
    const int wm   = warp >> 1;
    const int wn   = warp & 1;
    const int bm   = blockIdx.y * 128;
    const int bn   = blockIdx.x * 128;

    const int arow = tid >> 2;
    const int acol = (tid & 3) * 8;
    const int brow = tid >> 4;
    const int bcol = (tid & 15) * 8;

    const __nv_bfloat16* AgH = Ahi + (size_t)(bm + arow) * K + acol;
    const __nv_bfloat16* AgL = Alo + (size_t)(bm + arow) * K + acol;
    const __nv_bfloat16* BgH = Bhi + (size_t)brow * N + bn + bcol;
    const __nv_bfloat16* BgL = Blo + (size_t)brow * N + bn + bcol;

    const uint32_t saBase = (uint32_t)__cvta_generic_to_shared(
        &sA[arow * A_ST + acol]);
    const uint32_t sbBase = (uint32_t)__cvta_generic_to_shared(
        &sB[brow * B_ST + bcol]);

    float acc[2][8][4];
#pragma unroll
    for (int i = 0; i < 2; i++)
#pragma unroll
        for (int j = 0; j < 8; j++)
#pragma unroll
            for (int l = 0; l < 4; l++) acc[i][j][l] = 0.0f;

    const int KT = K / GBK;

#define ISSUE_TILE3(kt, buf)                                                  \
    do {                                                                      \
        const size_t ka = (size_t)(kt) * GBK;                                 \
        const size_t kb = (size_t)(kt) * GBK * N;                             \
        const uint32_t aOff = (buf) * (2 * A_MAT * 2);                        \
        const uint32_t bOff = (buf) * (2 * B_MAT * 2);                        \
        cp16(saBase + aOff, AgH + ka);                                        \
        cp16(saBase + aOff + 64 * A_ST * 2, AgH + ka + (size_t)64 * K);       \
        cp16(saBase + aOff + A_MAT * 2, AgL + ka);                            \
        cp16(saBase + aOff + A_MAT * 2 + 64 * A_ST * 2,                       \
             AgL + ka + (size_t)64 * K);                                      \
        cp16(sbBase + bOff, BgH + kb);                                        \
        cp16(sbBase + bOff + 16 * B_ST * 2, BgH + kb + (size_t)16 * N);       \
        cp16(sbBase + bOff + B_MAT * 2, BgL + kb);                            \
        cp16(sbBase + bOff + B_MAT * 2 + 16 * B_ST * 2,                       \
             BgL + kb + (size_t)16 * N);                                      \
        asm volatile("cp.async.commit_group;");                               \
    } while (0)

    ISSUE_TILE3(0, 0);

    for (int kt = 0; kt < KT; kt++) {
        const int buf = kt & 1;
        if (kt + 1 < KT) {
            ISSUE_TILE3(kt + 1, buf ^ 1);
            asm volatile("cp.async.wait_group 1;");
        } else {
            asm volatile("cp.async.wait_group 0;");
        }
        __syncthreads();

        const __nv_bfloat16* cAhi = sA + buf * 2 * A_MAT;
        const __nv_bfloat16* cAlo = cAhi + A_MAT;
        const __nv_bfloat16* cBhi = sB + buf * 2 * B_MAT;
        const __nv_bfloat16* cBlo = cBhi + B_MAT;

#pragma unroll
        for (int ks = 0; ks < 2; ks++) {
            uint32_t aH[2][4], aL[2][4];
#pragma unroll
            for (int mt = 0; mt < 2; mt++) {
                int row = wm * 32 + mt * 16 + (lane & 15);
                int col = ks * 16 + (lane >> 4) * 8;
                ldsm_x4(aH[mt], (uint32_t)__cvta_generic_to_shared(
                                    &cAhi[row * A_ST + col]));
                ldsm_x4(aL[mt], (uint32_t)__cvta_generic_to_shared(
                                    &cAlo[row * A_ST + col]));
            }
#pragma unroll
            for (int nt = 0; nt < 4; nt++) {
                int krow = ks * 16 + (lane & 15);
                int ncol = wn * 64 + nt * 16 + (lane >> 4) * 8;
                uint32_t bH[4], bL[4];
                ldsm_x4_t(bH, (uint32_t)__cvta_generic_to_shared(
                                  &cBhi[krow * B_ST + ncol]));
                ldsm_x4_t(bL, (uint32_t)__cvta_generic_to_shared(
                                  &cBlo[krow * B_ST + ncol]));
#pragma unroll
                for (int mt = 0; mt < 2; mt++) {
                    float* a0 = acc[mt][nt * 2 + 0];
                    float* a1 = acc[mt][nt * 2 + 1];
                    mma_bf16(a0, aH[mt], bH[0], bH[1]);
                    mma_bf16(a1, aH[mt], bH[2], bH[3]);
                    mma_bf16(a0, aH[mt], bL[0], bL[1]);
                    mma_bf16(a1, aH[mt], bL[2], bL[3]);
                    mma_bf16(a0, aL[mt], bH[0], bH[1]);
                    mma_bf16(a1, aL[mt], bH[2], bH[3]);
                }
            }
        }
        __syncthreads();
    }
#undef ISSUE_TILE3

#pragma unroll
    for (int mt = 0; mt < 2; mt++) {
        const int r0 = bm + wm * 32 + mt * 16 + (lane >> 2);
#pragma unroll
        for (int nt8 = 0; nt8 < 8; nt8++) {
            const int col = bn + wn * 64 + nt8 * 8 + (lane & 3) * 2;
            const float bx = __ldg(&bias[col]);
            const float by = __ldg(&bias[col + 1]);
            float v0 = gelu_exact(acc[mt][nt8][0] + bx);
            float v1 = gelu_exact(acc[mt][nt8][1] + by);
            float v2 = gelu_exact(acc[mt][nt8][2] + bx);
            float v3 = gelu_exact(acc[mt][nt8][3] + by);
            *(__half2*)(outH + (size_t)r0 * N + col)       = __floats2half2_rn(v0, v1);
            *(__half2*)(outH + (size_t)(r0 + 8) * N + col) = __floats2half2_rn(v2, v3);
        }
    }
}

// ---------------------------------------------------------------------------
// GEMM4: plain fp16 tensor-core GEMM, fp32 accumulate, fp32 out + bias.
// CTA 128x128, BK=32, double-buffered cp.async (same proven structure).
// ---------------------------------------------------------------------------
__global__ void __launch_bounds__(256, 2)
h16_gemm_kernel(const __half* __restrict__ A, const __half* __restrict__ B,
                const float* __restrict__ bias, float* __restrict__ C,
                int M, int N, int K)
{
    __shared__ __half sA[2][A_MAT];
    __shared__ __half sB[2][B_MAT];

    const int tid  = threadIdx.x;
    const int lane = tid & 31;
    const int warp = tid >> 5;
    const int wm   = warp >> 1;
    const int wn   = warp & 1;
    const int bm   = blockIdx.y * 128;
    const int bn   = blockIdx.x * 128;

    const int arow = tid >> 2;
    const int acol = (tid & 3) * 8;
    const int brow = tid >> 4;
    const int bcol = (tid & 15) * 8;

    const __half* Ag = A + (size_t)(bm + arow) * K + acol;
    const __half* Bg = B + (size_t)brow * N + bn + bcol;

    const uint32_t sa0 = (uint32_t)__cvta_generic_to_shared(&sA[0][arow * A_ST + acol]);
    const uint32_t sa1 = (uint32_t)__cvta_generic_to_shared(&sA[1][arow * A_ST + acol]);
    const uint32_t sb0 = (uint32_t)__cvta_generic_to_shared(&sB[0][brow * B_ST + bcol]);
    const uint32_t sb1 = (uint32_t)__cvta_generic_to_shared(&sB[1][brow * B_ST + bcol]);

    float acc[2][8][4];
#pragma unroll
    for (int i = 0; i < 2; i++)
#pragma unroll
        for (int j = 0; j < 8; j++)
#pragma unroll
            for (int l = 0; l < 4; l++) acc[i][j][l] = 0.0f;

    const int KT = K / GBK;

#define ISSUE_TILE4(kt, sa, sb)                                              \
    do {                                                                     \
        const __half* ag = Ag + (size_t)(kt) * GBK;                          \
        const __half* bg = Bg + (size_t)(kt) * GBK * N;                      \
        cp16((sa), ag);                                                      \
        cp16((sa) + 64 * A_ST * 2, ag + (size_t)64 * K);                     \
        cp16((sb), bg);                                                      \
        cp16((sb) + 16 * B_ST * 2, bg + (size_t)16 * N);                     \
        asm volatile("cp.async.commit_group;");                              \
    } while (0)

    ISSUE_TILE4(0, sa0, sb0);

    for (int kt = 0; kt < KT; kt++) {
        const int buf = kt & 1;
        if (kt + 1 < KT) {
            if (buf == 0) ISSUE_TILE4(kt + 1, sa1, sb1);
            else          ISSUE_TILE4(kt + 1, sa0, sb0);
            asm volatile("cp.async.wait_group 1;");
        } else {
            asm volatile("cp.async.wait_group 0;");
        }
        __syncthreads();

        const __half* cA = sA[buf];
        const __half* cB = sB[buf];

#pragma unroll
        for (int ks = 0; ks < 2; ks++) {
            uint32_t afr[2][4];
#pragma unroll
            for (int mt = 0; mt < 2; mt++) {
                int row = wm * 32 + mt * 16 + (lane & 15);
                int col = ks * 16 + (lane >> 4) * 8;
                ldsm_x4(afr[mt], (uint32_t)__cvta_generic_to_shared(
                                     &cA[row * A_ST + col]));
            }
#pragma unroll
            for (int nt = 0; nt < 4; nt++) {
                int krow = ks * 16 + (lane & 15);
                int ncol = wn * 64 + nt * 16 + (lane >> 4) * 8;
                uint32_t bfr[4];
                ldsm_x4_t(bfr, (uint32_t)__cvta_generic_to_shared(
                                   &cB[krow * B_ST + ncol]));
#pragma unroll
                for (int mt = 0; mt < 2; mt++) {
                    mma_f16(acc[mt][nt * 2 + 0], afr[mt], bfr[0], bfr[1]);
                    mma_f16(acc[mt][nt * 2 + 1], afr[mt], bfr[2], bfr[3]);
                }
            }
        }
        __syncthreads();
    }
#undef ISSUE_TILE4

#pragma unroll
    for (int mt = 0; mt < 2; mt++) {
        const int r0 = bm + wm * 32 + mt * 16 + (lane >> 2);
#pragma unroll
        for (int nt8 = 0; nt8 < 8; nt8++) {
            const int col = bn + wn * 64 + nt8 * 8 + (lane & 3) * 2;
            const float bx = __ldg(&bias[col]);
            const float by = __ldg(&bias[col + 1]);
            *(float2*)(C + (size_t)r0 * N + col) =
                make_float2(acc[mt][nt8][0] + bx, acc[mt][nt8][1] + by);
            *(float2*)(C + (size_t)(r0 + 8) * N + col) =
                make_float2(acc[mt][nt8][2] + bx, acc[mt][nt8][3] + by);
        }
    }
}

// ---------------------------------------------------------------------------
// e_sq, counts init
// ---------------------------------------------------------------------------
__global__ void esq_kernel(const float* __restrict__ cb, float* __restrict__ esq)
{
    int idx = blockIdx.x * blockDim.x + threadIdx.x;
    if (idx >= NC * NK) return;
    const float* e = cb + (size_t)idx * DPC;
    float s = 0.0f;
#pragma unroll
    for (int d = 0; d < DPC; d++) s += e[d] * e[d];
    esq[idx] = s;
}

__global__ void zero_counts_kernel(int* __restrict__ counts)
{
    int idx = blockIdx.x * blockDim.x + threadIdx.x;
    if (idx < NC * NK) counts[idx] = 0;
}

// ---------------------------------------------------------------------------
// VQ: fp32 argmin (exact), z_q emitted as split bf16 (hi, lo)
// ---------------------------------------------------------------------------
#define VQ_TB 128
#define VQ_KC 128

__global__ void __launch_bounds__(VQ_TB)
vq_kernel(const float* __restrict__ z, const float* __restrict__ codebooks,
          const float* __restrict__ esq,
          __nv_bfloat16* __restrict__ zqHi, __nv_bfloat16* __restrict__ zqLo,
          float* __restrict__ out_idx, float* __restrict__ partials,
          int* __restrict__ counts)
{
    __shared__ float E[VQ_KC][DPC];
    __shared__ float Esq_s[VQ_KC];
    __shared__ float red[VQ_TB];

    const int c   = blockIdx.y;
    const int tid = threadIdx.x;
    const int t   = blockIdx.x * VQ_TB + tid;

    float zr[DPC];
    {
        const float4* zp = (const float4*)(z + (size_t)t * D_E + c * DPC);
#pragma unroll
        for (int q = 0; q < DPC / 4; q++) {
            float4 v = zp[q];
            zr[4 * q + 0] = v.x; zr[4 * q + 1] = v.y;
            zr[4 * q + 2] = v.z; zr[4 * q + 3] = v.w;
        }
    }
    float zsq = 0.0f;
#pragma unroll
    for (int d = 0; d < DPC; d++) zsq = fmaf(zr[d], zr[d], zsq);

    const float* cb = codebooks + (size_t)c * NK * DPC;

    float best = 3.4e38f;
    int   bidx = 0;

    for (int k0 = 0; k0 < NK; k0 += VQ_KC) {
        for (int i = tid; i < VQ_KC * (DPC / 4); i += VQ_TB) {
            int row = i >> 4;
            int q   = i & 15;
            float4 v = *(const float4*)(cb + (size_t)(k0 + row) * DPC + q * 4);
            *(float4*)&E[row][q * 4] = v;
        }
        Esq_s[tid] = esq[c * NK + k0 + tid];
        __syncthreads();

        for (int j = 0; j < VQ_KC; j++) {
            float d0 = 0.f, d1 = 0.f, d2 = 0.f, d3 = 0.f;
#pragma unroll
            for (int d = 0; d < DPC; d += 4) {
                d0 = fmaf(zr[d + 0], E[j][d + 0], d0);
                d1 = fmaf(zr[d + 1], E[j][d + 1], d1);
                d2 = fmaf(zr[d + 2], E[j][d + 2], d2);
                d3 = fmaf(zr[d + 3], E[j][d + 3], d3);
            }
            float dot  = (d0 + d1) + (d2 + d3);
            float dist = zsq - 2.0f * dot + Esq_s[j];
            if (dist < best) { best = dist; bidx = k0 + j; }
        }
        __syncthreads();
    }

    const float* e = cb + (size_t)bidx * DPC;
    __nv_bfloat16* zh = zqHi + (size_t)t * D_E + c * DPC;
    __nv_bfloat16* zl = zqLo + (size_t)t * D_E + c * DPC;
    float cs = 0.0f;
#pragma unroll
    for (int q = 0; q < DPC / 4; q++) {
        float4 ev = *(const float4*)(e + q * 4);
        __nv_bfloat16 hx = __float2bfloat16_rn(ev.x);
        __nv_bfloat16 hy = __float2bfloat16_rn(ev.y);
        __nv_bfloat16 hz = __float2bfloat16_rn(ev.z);
        __nv_bfloat16 hw = __float2bfloat16_rn(ev.w);
        *(__nv_bfloat162*)(zh + 4 * q)     = __nv_bfloat162(hx, hy);
        *(__nv_bfloat162*)(zh + 4 * q + 2) = __nv_bfloat162(hz, hw);
        *(__nv_bfloat162*)(zl + 4 * q) = __nv_bfloat162(
            __float2bfloat16_rn(ev.x - __bfloat162float(hx)),
            __float2bfloat16_rn(ev.y - __bfloat162float(hy)));
        *(__nv_bfloat162*)(zl + 4 * q + 2) = __nv_bfloat162(
            __float2bfloat16_rn(ev.z - __bfloat162float(hz)),
            __float2bfloat16_rn(ev.w - __bfloat162float(hw)));
        float dx = zr[4 * q + 0] - ev.x;
        float dy = zr[4 * q + 1] - ev.y;
        float dz = zr[4 * q + 2] - ev.z;
        float dw = zr[4 * q + 3] - ev.w;
        cs += dx * dx + dy * dy + dz * dz + dw * dw;
    }

    atomicAdd(&counts[c * NK + bidx], 1);
    out_idx[(size_t)t * NC + c] = (float)bidx;

    red[tid] = cs;
    __syncthreads();
    for (int s = VQ_TB / 2; s > 0; s >>= 1) {
        if (tid < s) red[tid] += red[tid + s];
        __syncthreads();
    }
    if (tid == 0) partials[blockIdx.y * gridDim.x + blockIdx.x] = red[0];
}

// ---------------------------------------------------------------------------
// Finalize scalars
// ---------------------------------------------------------------------------
__global__ void __launch_bounds__(256)
finalize_kernel(const float* __restrict__ partials, int npart,
                const int* __restrict__ counts, float* __restrict__ out_scalars)
{
    __shared__ float sm[256];
    const int tid = threadIdx.x;

    float v = (tid < npart) ? partials[tid] : 0.0f;
    sm[tid] = v;
    __syncthreads();
    for (int s = 128; s > 0; s >>= 1) {
        if (tid < s) sm[tid] += sm[tid + s];
        __syncthreads();
    }
    if (tid == 0) {
        float commitment = 0.25f * sm[0] / (float)(T_TOKENS * D_E);
        out_scalars[0] = commitment;
        out_scalars[1] = commitment;
    }

    float ent_acc = 0.0f;
    for (int c = 0; c < NC; c++) {
        float s = 0.0f;
        for (int k = tid; k < NK; k += 256) {
            float p = (float)counts[c * NK + k] * (1.0f / 8192.0f);
            s -= p * logf(p + 1e-10f);
        }
        __syncthreads();
        sm[tid] = s;
        __syncthreads();
        for (int st = 128; st > 0; st >>= 1) {
            if (tid < st) sm[tid] += sm[tid + st];
            __syncthreads();
        }
        if (tid == 0) ent_acc += sm[0];
        __syncthreads();
    }
    if (tid == 0) out_scalars[2] = ent_acc * 0.25f;
}

// ---------------------------------------------------------------------------
// Host launcher. Inputs: x, W1, b1, W2, b2, codebooks, W3, b3, W4, b4
// ---------------------------------------------------------------------------
extern "C" void kernel_launch(void* const* d_in, const int* in_sizes, int n_in,
                              void* d_out, int out_size)
{
    const float* x   = (const float*)d_in[0];
    const float* W1  = (const float*)d_in[1];
    const float* b1  = (const float*)d_in[2];
    const float* W2  = (const float*)d_in[3];
    const float* b2  = (const float*)d_in[4];
    const float* cb  = (const float*)d_in[5];
    const float* W3  = (const float*)d_in[6];
    const float* b3  = (const float*)d_in[7];
    const float* W4  = (const float*)d_in[8];
    const float* b4  = (const float*)d_in[9];

    float* out = (float*)d_out;

    float *h1, *z, *esq, *part;
    __nv_bfloat16 *zqH, *zqL, *w3H, *w3L;
    __half *h3h, *w4h;
    int* counts;
    cudaGetSymbolAddress((void**)&h1,  g_h1);
    cudaGetSymbolAddress((void**)&z,   g_z);
    cudaGetSymbolAddress((void**)&zqH, g_zq_hi);
    cudaGetSymbolAddress((void**)&zqL, g_zq_lo);
    cudaGetSymbolAddress((void**)&h3h, g_h3_h);
    cudaGetSymbolAddress((void**)&w3H, g_w3_hi);
    cudaGetSymbolAddress((void**)&w3L, g_w3_lo);
    cudaGetSymbolAddress((void**)&w4h, g_w4_h);
    cudaGetSymbolAddress((void**)&esq, g_esq);
    cudaGetSymbolAddress((void**)&part, g_part);
    cudaGetSymbolAddress((void**)&counts, g_counts);

    cudaFuncSetAttribute(split_gemm3_kernel,
                         cudaFuncAttributeMaxDynamicSharedMemorySize,
                         SMEM_SPLIT_BYTES);

    // 0) weight conversions
    {
        int n3 = D_E * D_H3;
        int n4 = D_H3 * D_OUT;
        f2bf_split_kernel<<<(n3 / 4 + 255) / 256, 256>>>(W3, w3H, w3L, n3);
        f2h_kernel<<<(n4 / 4 + 255) / 256, 256>>>(W4, w4h, n4);
    }

    // 1) h1 = gelu(x @ W1 + b1)   3xTF32 (near-fp32 exact)
    tf32_gemm_kernel<<<dim3(D_H1 / 128, T_TOKENS / 128), 256>>>(
        x, W1, b1, h1, T_TOKENS, D_H1, D_IN, 1);

    // 2) z = h1 @ W2 + b2         3xTF32 (near-fp32 exact)
    tf32_gemm_kernel<<<dim3(D_E / 128, T_TOKENS / 128), 256>>>(
        h1, W2, b2, z, T_TOKENS, D_E, D_H1, 0);

    // 3) code norms + zero counts
    esq_kernel<<<(NC * NK + 255) / 256, 256>>>(cb, esq);
    zero_counts_kernel<<<(NC * NK + 255) / 256, 256>>>(counts);

    // 4) VQ (fp32 argmin, split-bf16 z_q)
    vq_kernel<<<dim3(T_TOKENS / VQ_TB, NC), VQ_TB>>>(
        z, cb, esq, zqH, zqL, out + XVQ_ELEMS, part, counts);

    // 5) scalars
    finalize_kernel<<<1, 256>>>(part, (T_TOKENS / VQ_TB) * NC, counts,
                                out + XVQ_ELEMS + IDX_ELEMS);

    // 6) h3 = gelu(zq @ W3 + b3)  split-bf16 3-term -> fp16 h3
    split_gemm3_kernel<<<dim3(D_H3 / 128, T_TOKENS / 128), 256,
                         SMEM_SPLIT_BYTES>>>(
        zqH, zqL, w3H, w3L, b3, h3h, T_TOKENS, D_H3, D_E);

    // 7) x_vq = h3 @ W4 + b4 -> out  plain fp16 tensor cores
    h16_gemm_kernel<<<dim3(D_OUT / 128, T_TOKENS / 128), 256>>>(
        h3h, w4h, b4, out, T_TOKENS, D_OUT, D_H3);
}

// round 8
// speedup vs baseline: 6.2641x; 1.2380x over previous
#include <cuda_runtime.h>
#include <cuda_bf16.h>
#include <cuda_fp16.h>
#include <math.h>
#include <stdint.h>

// ---------------------------------------------------------------------------
// Constants: T=8192; D_IN=1152, 4D_IN=4608, D_E=256, C=4, K=2048, dpc=64,
// H=4096, 4H=16384.
// Output (fp32): x_vq [8192*4096] | idx [8192*4] | total, commitment, entropy
// ---------------------------------------------------------------------------
#define T_TOKENS 8192
#define D_IN     1152
#define D_H1     4608
#define D_E      256
#define NC       4
#define NK       2048
#define DPC      64
#define D_H3     16384
#define D_OUT    4096

#define XVQ_ELEMS   (T_TOKENS * D_OUT)
#define IDX_ELEMS   (T_TOKENS * NC)

// Scratch (device globals)
__device__ __half g_x_hi [(size_t)T_TOKENS * D_IN];
__device__ __half g_x_lo [(size_t)T_TOKENS * D_IN];
__device__ __half g_w1_hi[(size_t)D_IN * D_H1];
__device__ __half g_w1_lo[(size_t)D_IN * D_H1];
__device__ __half g_w2_hi[(size_t)D_H1 * D_E];
__device__ __half g_w2_lo[(size_t)D_H1 * D_E];
__device__ __half g_h1_hi[(size_t)T_TOKENS * D_H1];
__device__ __half g_h1_lo[(size_t)T_TOKENS * D_H1];
__device__ float  g_z    [(size_t)T_TOKENS * D_E];
__device__ __half g_zq_h [(size_t)T_TOKENS * D_E];
__device__ __half g_w3_h [(size_t)D_E * D_H3];
__device__ __half g_h3_h [(size_t)T_TOKENS * D_H3];
__device__ __half g_w4_h [(size_t)D_H3 * D_OUT];
__device__ float g_esq[NC * NK];
__device__ int   g_counts[NC * NK];
__device__ float g_part[256];

__device__ __forceinline__ float gelu_exact(float x) {
    return 0.5f * x * (1.0f + erff(x * 0.70710678118654752440f));
}

// ---------------------------------------------------------------------------
// fp32 -> (fp16 hi, fp16 lo) split conversion
// ---------------------------------------------------------------------------
__global__ void f2h_split_kernel(const float* __restrict__ in,
                                 __half* __restrict__ hi,
                                 __half* __restrict__ lo, int n)
{
    int i = (blockIdx.x * blockDim.x + threadIdx.x) * 4;
    if (i >= n) return;
    float4 v = *(const float4*)(in + i);
    __half hx = __float2half_rn(v.x);
    __half hy = __float2half_rn(v.y);
    __half hz = __float2half_rn(v.z);
    __half hw = __float2half_rn(v.w);
    *(__half2*)(hi + i)     = __half2(hx, hy);
    *(__half2*)(hi + i + 2) = __half2(hz, hw);
    *(__half2*)(lo + i) = __half2(
        __float2half_rn(v.x - __half2float(hx)),
        __float2half_rn(v.y - __half2float(hy)));
    *(__half2*)(lo + i + 2) = __half2(
        __float2half_rn(v.z - __half2float(hz)),
        __float2half_rn(v.w - __half2float(hw)));
}

// ---------------------------------------------------------------------------
// fp32 -> fp16 conversion (W3, W4)
// ---------------------------------------------------------------------------
__global__ void f2h_kernel(const float* __restrict__ in,
                           __half* __restrict__ out, int n)
{
    int i = (blockIdx.x * blockDim.x + threadIdx.x) * 4;
    if (i >= n) return;
    float4 v = *(const float4*)(in + i);
    *(__half2*)(out + i)     = __floats2half2_rn(v.x, v.y);
    *(__half2*)(out + i + 2) = __floats2half2_rn(v.z, v.w);
}

// ---------------------------------------------------------------------------
// Shared smem-layout constants for 16-bit GEMMs
// ---------------------------------------------------------------------------
#define GBK 32
#define A_ST 40
#define B_ST 136
#define A_MAT (128 * A_ST)
#define B_MAT (GBK * B_ST)
#define SMEM_SPLIT_BYTES ((2 * 2 * A_MAT + 2 * 2 * B_MAT) * 2)

__device__ __forceinline__ void ldsm_x4(uint32_t* r, uint32_t addr) {
    asm volatile("ldmatrix.sync.aligned.m8n8.x4.shared.b16 {%0,%1,%2,%3}, [%4];"
                 : "=r"(r[0]), "=r"(r[1]), "=r"(r[2]), "=r"(r[3]) : "r"(addr));
}
__device__ __forceinline__ void ldsm_x4_t(uint32_t* r, uint32_t addr) {
    asm volatile("ldmatrix.sync.aligned.m8n8.x4.trans.shared.b16 {%0,%1,%2,%3}, [%4];"
                 : "=r"(r[0]), "=r"(r[1]), "=r"(r[2]), "=r"(r[3]) : "r"(addr));
}
__device__ __forceinline__ void mma_f16(float* d, const uint32_t* a,
                                        uint32_t b0, uint32_t b1) {
    asm volatile(
        "mma.sync.aligned.m16n8k16.row.col.f32.f16.f16.f32 "
        "{%0,%1,%2,%3},{%4,%5,%6,%7},{%8,%9},{%0,%1,%2,%3};"
        : "+f"(d[0]), "+f"(d[1]), "+f"(d[2]), "+f"(d[3])
        : "r"(a[0]), "r"(a[1]), "r"(a[2]), "r"(a[3]), "r"(b0), "r"(b1));
}
__device__ __forceinline__ void cp16(uint32_t saddr, const void* g) {
    asm volatile("cp.async.cg.shared.global [%0], [%1], 16;"
                 :: "r"(saddr), "l"(g));
}

// ---------------------------------------------------------------------------
// 3-term split-fp16 GEMM (GEMM1/GEMM2): ~fp32 accuracy on tensor cores.
// acc += Ah*Bh + Ah*Bl + Al*Bh   (fp32 accumulate; 22-bit operands)
// CTA 128x128, BK=32, 8 warps. mode 0: fp32 out. mode 1: gelu -> split fp16.
// ---------------------------------------------------------------------------
__global__ void __launch_bounds__(256, 2)
splitf16_gemm_kernel(const __half* __restrict__ Ahi,
                     const __half* __restrict__ Alo,
                     const __half* __restrict__ Bhi,
                     const __half* __restrict__ Blo,
                     const float* __restrict__ bias,
                     float* __restrict__ outF,
                     __half* __restrict__ outHi,
                     __half* __restrict__ outLo,
                     int M, int N, int K, int mode)
{
    extern __shared__ __half smem[];
    __half* sA = smem;
    __half* sB = smem + 4 * A_MAT;

    const int tid  = threadIdx.x;
    const int lane = tid & 31;
    const int warp = tid >> 5;
    const int wm   = warp >> 1;
    const int wn   = warp & 1;
    const int bm   = blockIdx.y * 128;
    const int bn   = blockIdx.x * 128;

    const int arow = tid >> 2;
    const int acol = (tid & 3) * 8;
    const int brow = tid >> 4;
    const int bcol = (tid & 15) * 8;

    const __half* AgH = Ahi + (size_t)(bm + arow) * K + acol;
    const __half* AgL = Alo + (size_t)(bm + arow) * K + acol;
    const __half* BgH = Bhi + (size_t)brow * N + bn + bcol;
    const __half* BgL = Blo + (size_t)brow * N + bn + bcol;

    const uint32_t saBase = (uint32_t)__cvta_generic_to_shared(
        &sA[arow * A_ST + acol]);
    const uint32_t sbBase = (uint32_t)__cvta_generic_to_shared(
        &sB[brow * B_ST + bcol]);

    float acc[2][8][4];
#pragma unroll
    for (int i = 0; i < 2; i++)
#pragma unroll
        for (int j = 0; j < 8; j++)
#pragma unroll
            for (int l = 0; l < 4; l++) acc[i][j][l] = 0.0f;

    const int KT = K / GBK;

#define ISSUE_SPLIT(kt, buf)                                                  \
    do {                                                                      \
        const size_t ka = (size_t)(kt) * GBK;                                 \
        const size_t kb = (size_t)(kt) * GBK * N;                             \
        const uint32_t aOff = (buf) * (2 * A_MAT * 2);                        \
        const uint32_t bOff = (buf) * (2 * B_MAT * 2);                        \
        cp16(saBase + aOff, AgH + ka);                                        \
        cp16(saBase + aOff + 64 * A_ST * 2, AgH + ka + (size_t)64 * K);       \
        cp16(saBase + aOff + A_MAT * 2, AgL + ka);                            \
        cp16(saBase + aOff + A_MAT * 2 + 64 * A_ST * 2,                       \
             AgL + ka + (size_t)64 * K);                                      \
        cp16(sbBase + bOff, BgH + kb);                                        \
        cp16(sbBase + bOff + 16 * B_ST * 2, BgH + kb + (size_t)16 * N);       \
        cp16(sbBase + bOff + B_MAT * 2, BgL + kb);                            \
        cp16(sbBase + bOff + B_MAT * 2 + 16 * B_ST * 2,                       \
             BgL + kb + (size_t)16 * N);                                      \
        asm volatile("cp.async.commit_group;");                               \
    } while (0)

    ISSUE_SPLIT(0, 0);

    for (int kt = 0; kt < KT; kt++) {
        const int buf = kt & 1;
        if (kt + 1 < KT) {
            ISSUE_SPLIT(kt + 1, buf ^ 1);
            asm volatile("cp.async.wait_group 1;");
        } else {
            asm volatile("cp.async.wait_group 0;");
        }
        __syncthreads();

        const __half* cAhi = sA + buf * 2 * A_MAT;
        const __half* cAlo = cAhi + A_MAT;
        const __half* cBhi = sB + buf * 2 * B_MAT;
        const __half* cBlo = cBhi + B_MAT;

#pragma unroll
        for (int ks = 0; ks < 2; ks++) {
            uint32_t aH[2][4], aL[2][4];
#pragma unroll
            for (int mt = 0; mt < 2; mt++) {
                int row = wm * 32 + mt * 16 + (lane & 15);
                int col = ks * 16 + (lane >> 4) * 8;
                ldsm_x4(aH[mt], (uint32_t)__cvta_generic_to_shared(
                                    &cAhi[row * A_ST + col]));
                ldsm_x4(aL[mt], (uint32_t)__cvta_generic_to_shared(
                                    &cAlo[row * A_ST + col]));
            }
#pragma unroll
            for (int nt = 0; nt < 4; nt++) {
                int krow = ks * 16 + (lane & 15);
                int ncol = wn * 64 + nt * 16 + (lane >> 4) * 8;
                uint32_t bH[4], bL[4];
                ldsm_x4_t(bH, (uint32_t)__cvta_generic_to_shared(
                                  &cBhi[krow * B_ST + ncol]));
                ldsm_x4_t(bL, (uint32_t)__cvta_generic_to_shared(
                                  &cBlo[krow * B_ST + ncol]));
#pragma unroll
                for (int mt = 0; mt < 2; mt++) {
                    float* a0 = acc[mt][nt * 2 + 0];
                    float* a1 = acc[mt][nt * 2 + 1];
                    mma_f16(a0, aH[mt], bH[0], bH[1]);
                    mma_f16(a1, aH[mt], bH[2], bH[3]);
                    mma_f16(a0, aH[mt], bL[0], bL[1]);
                    mma_f16(a1, aH[mt], bL[2], bL[3]);
                    mma_f16(a0, aL[mt], bH[0], bH[1]);
                    mma_f16(a1, aL[mt], bH[2], bH[3]);
                }
            }
        }
        __syncthreads();
    }
#undef ISSUE_SPLIT

#pragma unroll
    for (int mt = 0; mt < 2; mt++) {
        const int r0 = bm + wm * 32 + mt * 16 + (lane >> 2);
#pragma unroll
        for (int nt8 = 0; nt8 < 8; nt8++) {
            const int col = bn + wn * 64 + nt8 * 8 + (lane & 3) * 2;
            const float bx = __ldg(&bias[col]);
            const float by = __ldg(&bias[col + 1]);
            float v0 = acc[mt][nt8][0] + bx;
            float v1 = acc[mt][nt8][1] + by;
            float v2 = acc[mt][nt8][2] + bx;
            float v3 = acc[mt][nt8][3] + by;
            if (mode == 1) {
                v0 = gelu_exact(v0); v1 = gelu_exact(v1);
                v2 = gelu_exact(v2); v3 = gelu_exact(v3);
                __half h0 = __float2half_rn(v0);
                __half h1 = __float2half_rn(v1);
                __half h2 = __float2half_rn(v2);
                __half h3v = __float2half_rn(v3);
                *(__half2*)(outHi + (size_t)r0 * N + col) = __half2(h0, h1);
                *(__half2*)(outHi + (size_t)(r0 + 8) * N + col) = __half2(h2, h3v);
                *(__half2*)(outLo + (size_t)r0 * N + col) = __half2(
                    __float2half_rn(v0 - __half2float(h0)),
                    __float2half_rn(v1 - __half2float(h1)));
                *(__half2*)(outLo + (size_t)(r0 + 8) * N + col) = __half2(
                    __float2half_rn(v2 - __half2float(h2)),
                    __float2half_rn(v3 - __half2float(h3v)));
            } else {
                *(float2*)(outF + (size_t)r0 * N + col)       = make_float2(v0, v1);
                *(float2*)(outF + (size_t)(r0 + 8) * N + col) = make_float2(v2, v3);
            }
        }
    }
}

// ---------------------------------------------------------------------------
// Plain fp16 tensor-core GEMM (GEMM3/GEMM4), fp32 accumulate.
// mode 0: fp32 out + bias (GEMM4). mode 1: gelu -> fp16 out (GEMM3).
// ---------------------------------------------------------------------------
__global__ void __launch_bounds__(256, 2)
h16_gemm_kernel(const __half* __restrict__ A, const __half* __restrict__ B,
                const float* __restrict__ bias, float* __restrict__ outF,
                __half* __restrict__ outH, int M, int N, int K, int mode)
{
    __shared__ __half sA[2][A_MAT];
    __shared__ __half sB[2][B_MAT];

    const int tid  = threadIdx.x;
    const int lane = tid & 31;
    const int warp = tid >> 5;
    const int wm   = warp >> 1;
    const int wn   = warp & 1;
    const int bm   = blockIdx.y * 128;
    const int bn   = blockIdx.x * 128;

    const int arow = tid >> 2;
    const int acol = (tid & 3) * 8;
    const int brow = tid >> 4;
    const int bcol = (tid & 15) * 8;

    const __half* Ag = A + (size_t)(bm + arow) * K + acol;
    const __half* Bg = B + (size_t)brow * N + bn + bcol;

    const uint32_t sa0 = (uint32_t)__cvta_generic_to_shared(&sA[0][arow * A_ST + acol]);
    const uint32_t sa1 = (uint32_t)__cvta_generic_to_shared(&sA[1][arow * A_ST + acol]);
    const uint32_t sb0 = (uint32_t)__cvta_generic_to_shared(&sB[0][brow * B_ST + bcol]);
    const uint32_t sb1 = (uint32_t)__cvta_generic_to_shared(&sB[1][brow * B_ST + bcol]);

    float acc[2][8][4];
#pragma unroll
    for (int i = 0; i < 2; i++)
#pragma unroll
        for (int j = 0; j < 8; j++)
#pragma unroll
            for (int l = 0; l < 4; l++) acc[i][j][l] = 0.0f;

    const int KT = K / GBK;

#define ISSUE_H16(kt, sa, sb)                                                \
    do {                                                                     \
        const __half* ag = Ag + (size_t)(kt) * GBK;                          \
        const __half* bg = Bg + (size_t)(kt) * GBK * N;                      \
        cp16((sa), ag);                                                      \
        cp16((sa) + 64 * A_ST * 2, ag + (size_t)64 * K);                     \
        cp16((sb), bg);                                                      \
        cp16((sb) + 16 * B_ST * 2, bg + (size_t)16 * N);                     \
        asm volatile("cp.async.commit_group;");                              \
    } while (0)

    ISSUE_H16(0, sa0, sb0);

    for (int kt = 0; kt < KT; kt++) {
        const int buf = kt & 1;
        if (kt + 1 < KT) {
            if (buf == 0) ISSUE_H16(kt + 1, sa1, sb1);
            else          ISSUE_H16(kt + 1, sa0, sb0);
            asm volatile("cp.async.wait_group 1;");
        } else {
            asm volatile("cp.async.wait_group 0;");
        }
        __syncthreads();

        const __half* cA = sA[buf];
        const __half* cB = sB[buf];

#pragma unroll
        for (int ks = 0; ks < 2; ks++) {
            uint32_t afr[2][4];
#pragma unroll
            for (int mt = 0; mt < 2; mt++) {
                int row = wm * 32 + mt * 16 + (lane & 15);
                int col = ks * 16 + (lane >> 4) * 8;
                ldsm_x4(afr[mt], (uint32_t)__cvta_generic_to_shared(
                                     &cA[row * A_ST + col]));
            }
#pragma unroll
            for (int nt = 0; nt < 4; nt++) {
                int krow = ks * 16 + (lane & 15);
                int ncol = wn * 64 + nt * 16 + (lane >> 4) * 8;
                uint32_t bfr[4];
                ldsm_x4_t(bfr, (uint32_t)__cvta_generic_to_shared(
                                   &cB[krow * B_ST + ncol]));
#pragma unroll
                for (int mt = 0; mt < 2; mt++) {
                    mma_f16(acc[mt][nt * 2 + 0], afr[mt], bfr[0], bfr[1]);
                    mma_f16(acc[mt][nt * 2 + 1], afr[mt], bfr[2], bfr[3]);
                }
            }
        }
        __syncthreads();
    }
#undef ISSUE_H16

#pragma unroll
    for (int mt = 0; mt < 2; mt++) {
        const int r0 = bm + wm * 32 + mt * 16 + (lane >> 2);
#pragma unroll
        for (int nt8 = 0; nt8 < 8; nt8++) {
            const int col = bn + wn * 64 + nt8 * 8 + (lane & 3) * 2;
            const float bx = __ldg(&bias[col]);
            const float by = __ldg(&bias[col + 1]);
            float v0 = acc[mt][nt8][0] + bx;
            float v1 = acc[mt][nt8][1] + by;
            float v2 = acc[mt][nt8][2] + bx;
            float v3 = acc[mt][nt8][3] + by;
            if (mode == 1) {
                v0 = gelu_exact(v0); v1 = gelu_exact(v1);
                v2 = gelu_exact(v2); v3 = gelu_exact(v3);
                *(__half2*)(outH + (size_t)r0 * N + col) =
                    __floats2half2_rn(v0, v1);
                *(__half2*)(outH + (size_t)(r0 + 8) * N + col) =
                    __floats2half2_rn(v2, v3);
            } else {
                *(float2*)(outF + (size_t)r0 * N + col)       = make_float2(v0, v1);
                *(float2*)(outF + (size_t)(r0 + 8) * N + col) = make_float2(v2, v3);
            }
        }
    }
}

// ---------------------------------------------------------------------------
// e_sq, counts init
// ---------------------------------------------------------------------------
__global__ void esq_kernel(const float* __restrict__ cb, float* __restrict__ esq)
{
    int idx = blockIdx.x * blockDim.x + threadIdx.x;
    if (idx >= NC * NK) return;
    const float* e = cb + (size_t)idx * DPC;
    float s = 0.0f;
#pragma unroll
    for (int d = 0; d < DPC; d++) s += e[d] * e[d];
    esq[idx] = s;
}

__global__ void zero_counts_kernel(int* __restrict__ counts)
{
    int idx = blockIdx.x * blockDim.x + threadIdx.x;
    if (idx < NC * NK) counts[idx] = 0;
}

// ---------------------------------------------------------------------------
// VQ: fp32 argmin (exact), z_q emitted as fp16
// ---------------------------------------------------------------------------
#define VQ_TB 128
#define VQ_KC 128

__global__ void __launch_bounds__(VQ_TB)
vq_kernel(const float* __restrict__ z, const float* __restrict__ codebooks,
          const float* __restrict__ esq, __half* __restrict__ zqh,
          float* __restrict__ out_idx, float* __restrict__ partials,
          int* __restrict__ counts)
{
    __shared__ float E[VQ_KC][DPC];
    __shared__ float Esq_s[VQ_KC];
    __shared__ float red[VQ_TB];

    const int c   = blockIdx.y;
    const int tid = threadIdx.x;
    const int t   = blockIdx.x * VQ_TB + tid;

    float zr[DPC];
    {
        const float4* zp = (const float4*)(z + (size_t)t * D_E + c * DPC);
#pragma unroll
        for (int q = 0; q < DPC / 4; q++) {
            float4 v = zp[q];
            zr[4 * q + 0] = v.x; zr[4 * q + 1] = v.y;
            zr[4 * q + 2] = v.z; zr[4 * q + 3] = v.w;
        }
    }
    float zsq = 0.0f;
#pragma unroll
    for (int d = 0; d < DPC; d++) zsq = fmaf(zr[d], zr[d], zsq);

    const float* cb = codebooks + (size_t)c * NK * DPC;

    float best = 3.4e38f;
    int   bidx = 0;

    for (int k0 = 0; k0 < NK; k0 += VQ_KC) {
        for (int i = tid; i < VQ_KC * (DPC / 4); i += VQ_TB) {
            int row = i >> 4;
            int q   = i & 15;
            float4 v = *(const float4*)(cb + (size_t)(k0 + row) * DPC + q * 4);
            *(float4*)&E[row][q * 4] = v;
        }
        Esq_s[tid] = esq[c * NK + k0 + tid];
        __syncthreads();

        for (int j = 0; j < VQ_KC; j++) {
            float d0 = 0.f, d1 = 0.f, d2 = 0.f, d3 = 0.f;
#pragma unroll
            for (int d = 0; d < DPC; d += 4) {
                d0 = fmaf(zr[d + 0], E[j][d + 0], d0);
                d1 = fmaf(zr[d + 1], E[j][d + 1], d1);
                d2 = fmaf(zr[d + 2], E[j][d + 2], d2);
                d3 = fmaf(zr[d + 3], E[j][d + 3], d3);
            }
            float dot  = (d0 + d1) + (d2 + d3);
            float dist = zsq - 2.0f * dot + Esq_s[j];
            if (dist < best) { best = dist; bidx = k0 + j; }
        }
        __syncthreads();
    }

    const float* e = cb + (size_t)bidx * DPC;
    __half* zp = zqh + (size_t)t * D_E + c * DPC;
    float cs = 0.0f;
#pragma unroll
    for (int q = 0; q < DPC / 4; q++) {
        float4 ev = *(const float4*)(e + q * 4);
        *(__half2*)(zp + 4 * q)     = __floats2half2_rn(ev.x, ev.y);
        *(__half2*)(zp + 4 * q + 2) = __floats2half2_rn(ev.z, ev.w);
        float dx = zr[4 * q + 0] - ev.x;
        float dy = zr[4 * q + 1] - ev.y;
        float dz = zr[4 * q + 2] - ev.z;
        float dw = zr[4 * q + 3] - ev.w;
        cs += dx * dx + dy * dy + dz * dz + dw * dw;
    }

    atomicAdd(&counts[c * NK + bidx], 1);
    out_idx[(size_t)t * NC + c] = (float)bidx;

    red[tid] = cs;
    __syncthreads();
    for (int s = VQ_TB / 2; s > 0; s >>= 1) {
        if (tid < s) red[tid] += red[tid + s];
        __syncthreads();
    }
    if (tid == 0) partials[blockIdx.y * gridDim.x + blockIdx.x] = red[0];
}

// ---------------------------------------------------------------------------
// Finalize scalars
// ---------------------------------------------------------------------------
__global__ void __launch_bounds__(256)
finalize_kernel(const float* __restrict__ partials, int npart,
                const int* __restrict__ counts, float* __restrict__ out_scalars)
{
    __shared__ float sm[256];
    const int tid = threadIdx.x;

    float v = (tid < npart) ? partials[tid] : 0.0f;
    sm[tid] = v;
    __syncthreads();
    for (int s = 128; s > 0; s >>= 1) {
        if (tid < s) sm[tid] += sm[tid + s];
        __syncthreads();
    }
    if (tid == 0) {
        float commitment = 0.25f * sm[0] / (float)(T_TOKENS * D_E);
        out_scalars[0] = commitment;
        out_scalars[1] = commitment;
    }

    float ent_acc = 0.0f;
    for (int c = 0; c < NC; c++) {
        float s = 0.0f;
        for (int k = tid; k < NK; k += 256) {
            float p = (float)counts[c * NK + k] * (1.0f / 8192.0f);
            s -= p * logf(p + 1e-10f);
        }
        __syncthreads();
        sm[tid] = s;
        __syncthreads();
        for (int st = 128; st > 0; st >>= 1) {
            if (tid < st) sm[tid] += sm[tid + st];
            __syncthreads();
        }
        if (tid == 0) ent_acc += sm[0];
        __syncthreads();
    }
    if (tid == 0) out_scalars[2] = ent_acc * 0.25f;
}

// ---------------------------------------------------------------------------
// Host launcher. Inputs: x, W1, b1, W2, b2, codebooks, W3, b3, W4, b4
// ---------------------------------------------------------------------------
extern "C" void kernel_launch(void* const* d_in, const int* in_sizes, int n_in,
                              void* d_out, int out_size)
{
    const float* x   = (const float*)d_in[0];
    const float* W1  = (const float*)d_in[1];
    const float* b1  = (const float*)d_in[2];
    const float* W2  = (const float*)d_in[3];
    const float* b2  = (const float*)d_in[4];
    const float* cb  = (const float*)d_in[5];
    const float* W3  = (const float*)d_in[6];
    const float* b3  = (const float*)d_in[7];
    const float* W4  = (const float*)d_in[8];
    const float* b4  = (const float*)d_in[9];

    float* out = (float*)d_out;

    float *z, *esq, *part;
    __half *xH, *xL, *w1H, *w1L, *w2H, *w2L, *h1H, *h1L, *zqh, *w3h, *h3h, *w4h;
    int* counts;
    cudaGetSymbolAddress((void**)&xH,  g_x_hi);
    cudaGetSymbolAddress((void**)&xL,  g_x_lo);
    cudaGetSymbolAddress((void**)&w1H, g_w1_hi);
    cudaGetSymbolAddress((void**)&w1L, g_w1_lo);
    cudaGetSymbolAddress((void**)&w2H, g_w2_hi);
    cudaGetSymbolAddress((void**)&w2L, g_w2_lo);
    cudaGetSymbolAddress((void**)&h1H, g_h1_hi);
    cudaGetSymbolAddress((void**)&h1L, g_h1_lo);
    cudaGetSymbolAddress((void**)&z,   g_z);
    cudaGetSymbolAddress((void**)&zqh, g_zq_h);
    cudaGetSymbolAddress((void**)&w3h, g_w3_h);
    cudaGetSymbolAddress((void**)&h3h, g_h3_h);
    cudaGetSymbolAddress((void**)&w4h, g_w4_h);
    cudaGetSymbolAddress((void**)&esq, g_esq);
    cudaGetSymbolAddress((void**)&part, g_part);
    cudaGetSymbolAddress((void**)&counts, g_counts);

    cudaFuncSetAttribute(splitf16_gemm_kernel,
                         cudaFuncAttributeMaxDynamicSharedMemorySize,
                         SMEM_SPLIT_BYTES);

    // 0) conversions
    {
        int nx = T_TOKENS * D_IN;
        int n1 = D_IN * D_H1;
        int n2 = D_H1 * D_E;
        int n3 = D_E * D_H3;
        int n4 = D_H3 * D_OUT;
        f2h_split_kernel<<<(nx / 4 + 255) / 256, 256>>>(x, xH, xL, nx);
        f2h_split_kernel<<<(n1 / 4 + 255) / 256, 256>>>(W1, w1H, w1L, n1);
        f2h_split_kernel<<<(n2 / 4 + 255) / 256, 256>>>(W2, w2H, w2L, n2);
        f2h_kernel<<<(n3 / 4 + 255) / 256, 256>>>(W3, w3h, n3);
        f2h_kernel<<<(n4 / 4 + 255) / 256, 256>>>(W4, w4h, n4);
    }

    // 1) h1 = gelu(x @ W1 + b1)   split-fp16 3-term -> split-fp16 h1
    splitf16_gemm_kernel<<<dim3(D_H1 / 128, T_TOKENS / 128), 256,
                           SMEM_SPLIT_BYTES>>>(
        xH, xL, w1H, w1L, b1, nullptr, h1H, h1L,
        T_TOKENS, D_H1, D_IN, 1);

    // 2) z = h1 @ W2 + b2         split-fp16 3-term -> fp32 z
    splitf16_gemm_kernel<<<dim3(D_E / 128, T_TOKENS / 128), 256,
                           SMEM_SPLIT_BYTES>>>(
        h1H, h1L, w2H, w2L, b2, z, nullptr, nullptr,
        T_TOKENS, D_E, D_H1, 0);

    // 3) code norms + zero counts
    esq_kernel<<<(NC * NK + 255) / 256, 256>>>(cb, esq);
    zero_counts_kernel<<<(NC * NK + 255) / 256, 256>>>(counts);

    // 4) VQ (fp32 argmin, fp16 z_q)
    vq_kernel<<<dim3(T_TOKENS / VQ_TB, NC), VQ_TB>>>(
        z, cb, esq, zqh, out + XVQ_ELEMS, part, counts);

    // 5) scalars
    finalize_kernel<<<1, 256>>>(part, (T_TOKENS / VQ_TB) * NC, counts,
                                out + XVQ_ELEMS + IDX_ELEMS);

    // 6) h3 = gelu(zq @ W3 + b3)  plain fp16 -> fp16 h3
    h16_gemm_kernel<<<dim3(D_H3 / 128, T_TOKENS / 128), 256>>>(
        zqh, w3h, b3, nullptr, h3h, T_TOKENS, D_H3, D_E, 1);

    // 7) x_vq = h3 @ W4 + b4 -> out  plain fp16
    h16_gemm_kernel<<<dim3(D_OUT / 128, T_TOKENS / 128), 256>>>(
        h3h, w4h, b4, out, nullptr, T_TOKENS, D_OUT, D_H3, 0);
}